// round 12
// baseline (speedup 1.0000x reference)
#include <cuda_runtime.h>
#include <cuda_bf16.h>
#include <math.h>

#define T2   2048
#define HIDN 2048
#define NH   16
#define NKV  8
#define HD   128
#define II   8192
#define EPS  1e-6f
#define SCALE 0.08838834764831845f   // 1/sqrt(128)
#define PITCH 40                      // smem row pitch in bf16 (80B): ldmatrix/B-load conflict-free
#define BUFB  10240                   // one 128xPITCH bf16 buffer (bytes)

// ================= scratch (static device globals; no allocations) =================
__device__ __align__(256) float g_x  [(size_t)T2 * HIDN];
__device__ __align__(256) float g_q  [(size_t)T2 * NH  * HD];
__device__ __align__(256) float g_k  [(size_t)T2 * NKV * HD];
__device__ __align__(256) float g_v  [(size_t)T2 * NKV * HD];
__device__ __align__(256) float g_sc [(size_t)NH * T2 * T2];
__device__ __align__(256) float g_ao [(size_t)T2 * NH * HD];
__device__ __align__(256) float g_hid[(size_t)T2 * HIDN];
__device__ __align__(256) float g_gu [(size_t)T2 * 2 * II];
__device__ __align__(256) float g_h2 [(size_t)T2 * HIDN];

// bf16 split-concat buffers (A-pattern: hi|lo|hi ; B-pattern: hi|hi|lo)
__device__ __align__(256) __nv_bfloat16 c_h  [(size_t)T2 * 3 * HIDN];
__device__ __align__(256) __nv_bfloat16 c_h2 [(size_t)T2 * 3 * HIDN];
__device__ __align__(256) __nv_bfloat16 c_wq [(size_t)(NH * HD) * 3 * HIDN];
__device__ __align__(256) __nv_bfloat16 c_wk [(size_t)(NKV * HD) * 3 * HIDN];
__device__ __align__(256) __nv_bfloat16 c_wv [(size_t)(NKV * HD) * 3 * HIDN];
__device__ __align__(256) __nv_bfloat16 c_wo [(size_t)HIDN * 3 * (NH * HD)];
__device__ __align__(256) __nv_bfloat16 c_wgu[(size_t)(2 * II) * 3 * HIDN];
__device__ __align__(256) __nv_bfloat16 c_wd [(size_t)HIDN * 3 * II];
__device__ __align__(256) __nv_bfloat16 c_act[(size_t)T2 * 3 * II];
__device__ __align__(256) __nv_bfloat16 c_q  [(size_t)NH  * T2 * 3 * HD];
__device__ __align__(256) __nv_bfloat16 c_k  [(size_t)NKV * T2 * 3 * HD];
__device__ __align__(256) __nv_bfloat16 c_vt [(size_t)NKV * HD * 3 * T2];
__device__ __align__(256) __nv_bfloat16 c_p  [(size_t)NH * T2 * 3 * T2];
__device__ __align__(256) __nv_bfloat16 c_ao [(size_t)T2 * 3 * (NH * HD)];

// ================= mma.sync helpers (baseline PTX — compiles for sm_103) =================
__device__ __forceinline__ unsigned smem_u32(const void* p) {
    unsigned a;
    asm("{ .reg .u64 t; cvta.to.shared.u64 t, %1; cvt.u32.u64 %0, t; }" : "=r"(a) : "l"(p));
    return a;
}
__device__ __forceinline__ void ldsm4(unsigned* r, unsigned addr) {
    asm volatile("ldmatrix.sync.aligned.m8n8.x4.shared.b16 {%0,%1,%2,%3}, [%4];"
                 : "=r"(r[0]), "=r"(r[1]), "=r"(r[2]), "=r"(r[3]) : "r"(addr));
}
__device__ __forceinline__ void mma16816(float* c, const unsigned* a, const unsigned* b) {
    asm volatile(
        "mma.sync.aligned.m16n8k16.row.col.f32.bf16.bf16.f32 "
        "{%0,%1,%2,%3}, {%4,%5,%6,%7}, {%8,%9}, {%0,%1,%2,%3};"
        : "+f"(c[0]), "+f"(c[1]), "+f"(c[2]), "+f"(c[3])
        : "r"(a[0]), "r"(a[1]), "r"(a[2]), "r"(a[3]), "r"(b[0]), "r"(b[1]));
}
__device__ __forceinline__ void cp16(unsigned saddr, const void* gaddr) {
    asm volatile("cp.async.cg.shared.global [%0], [%1], 16;" :: "r"(saddr), "l"(gaddr));
}
__device__ __forceinline__ void cp_commit() {
    asm volatile("cp.async.commit_group;" ::: "memory");
}
__device__ __forceinline__ void cp_wait1() {
    asm volatile("cp.async.wait_group 1;" ::: "memory");
}

__device__ __forceinline__ void split2(float x, __nv_bfloat16& h, __nv_bfloat16& l) {
    h = __float2bfloat16_rn(x);
    l = __float2bfloat16_rn(x - __bfloat162float(h));
}

// ================= split-bf16 GEMM via mma.sync + cp.async 3-stage pipeline =================
// C[M,N](fp32) = A[M,Kp](bf16) * B[N,Kp](bf16)^T (+ Add), 128x128 tiles, K chunks of 32.
// causal!=0: skip tile entirely when n0 > m0+127 (output never read there).
// seg_len>0: Kp = 3 segments of seg_len chunks; only first min(seg_len,(by+1)*4)
//            chunks of each segment are nonzero (causal P) -> iterate those only.
__global__ void __launch_bounds__(256) gemm_bf16(
    const __nv_bfloat16* __restrict__ A, const __nv_bfloat16* __restrict__ B,
    const float* __restrict__ Add, float* __restrict__ C,
    int Kp, int lda, int ldb, int ldc, long sA, long sB, long sC, int bdiv,
    int causal, int seg_len)
{
    extern __shared__ char sm[];
    const int m0 = blockIdx.y * 128;
    const int n0 = blockIdx.x * 128;
    if (causal && n0 > m0 + 127) return;

    const int tid  = threadIdx.x;
    const int lane = tid & 31;
    const int wid  = tid >> 5;
    const int wm   = (wid & 1) * 64;
    const int wn   = (wid >> 1) * 32;

    const int bz = blockIdx.z;
    A += (long)bz * sA;
    B += (long)(bz / bdiv) * sB;
    C += (long)bz * sC;
    if (Add) Add += (long)bz * sC;

    const int lr0 = tid >> 2;
    const int lr1 = (tid >> 2) + 64;
    const int sg  = (tid & 3) * 8;

    const unsigned smb = smem_u32(sm);
    // per-thread smem targets (byte offsets within a buffer)
    const unsigned oa0 = (unsigned)(lr0 * PITCH + sg) * 2;
    const unsigned oa1 = (unsigned)(lr1 * PITCH + sg) * 2;

    const int nch   = Kp >> 5;
    const int valid = seg_len ? min(seg_len, (blockIdx.y + 1) * 4) : 0;
    const int nit   = seg_len ? 3 * valid : nch;

    float acc[4][4][4];
#pragma unroll
    for (int i = 0; i < 4; i++)
#pragma unroll
        for (int j = 0; j < 4; j++)
#pragma unroll
            for (int e = 0; e < 4; e++) acc[i][j][e] = 0.f;

    // issue chunk (by logical iteration it) into stage s
    auto issue = [&](int it, int s) {
        int ic = seg_len ? ((it / valid) * seg_len + (it % valid)) : it;
        const int k0 = ic * 32;
        unsigned ab = smb + (unsigned)s * BUFB;
        unsigned bb = smb + 3u * BUFB + (unsigned)s * BUFB;
        cp16(ab + oa0, A + (long)(m0 + lr0) * lda + k0 + sg);
        cp16(ab + oa1, A + (long)(m0 + lr1) * lda + k0 + sg);
        cp16(bb + oa0, B + (long)(n0 + lr0) * ldb + k0 + sg);
        cp16(bb + oa1, B + (long)(n0 + lr1) * ldb + k0 + sg);
    };

    // prologue: stages 0,1
    if (nit > 0) { issue(0, 0); } cp_commit();
    if (nit > 1) { issue(1, 1); } cp_commit();

    for (int it = 0; it < nit; it++) {
        const int buf = it % 3;
        cp_wait1();
        __syncthreads();
        if (it + 2 < nit) issue(it + 2, (it + 2) % 3);
        cp_commit();

        const unsigned ab = smb + (unsigned)buf * BUFB;
        const __nv_bfloat16* bsp = (const __nv_bfloat16*)(sm + 3 * BUFB + buf * BUFB);
#pragma unroll
        for (int kk = 0; kk < 32; kk += 16) {
            unsigned af[4][4];
#pragma unroll
            for (int mt = 0; mt < 4; mt++) {
                unsigned addr = ab + (unsigned)((wm + mt * 16 + (lane & 15)) * PITCH + kk + (lane >> 4) * 8) * 2;
                ldsm4(af[mt], addr);
            }
            unsigned bfr[4][2];
#pragma unroll
            for (int nt = 0; nt < 4; nt++) {
                const __nv_bfloat16* bp = bsp + (wn + nt * 8 + (lane >> 2)) * PITCH + kk + (lane & 3) * 2;
                bfr[nt][0] = *(const unsigned*)bp;
                bfr[nt][1] = *(const unsigned*)(bp + 8);
            }
#pragma unroll
            for (int mt = 0; mt < 4; mt++)
#pragma unroll
                for (int nt = 0; nt < 4; nt++)
                    mma16816(acc[mt][nt], af[mt], bfr[nt]);
        }
    }

    // epilogue
    const int er = lane >> 2;
    const int ec = (lane & 3) * 2;
#pragma unroll
    for (int mt = 0; mt < 4; mt++) {
        const int rA = m0 + wm + mt * 16 + er;
#pragma unroll
        for (int nt = 0; nt < 4; nt++) {
            const int cA = n0 + wn + nt * 8 + ec;
            float2 v0 = make_float2(acc[mt][nt][0], acc[mt][nt][1]);
            float2 v1 = make_float2(acc[mt][nt][2], acc[mt][nt][3]);
            if (Add) {
                float2 a0 = *(const float2*)(Add + (long)rA * ldc + cA);
                float2 a1 = *(const float2*)(Add + (long)(rA + 8) * ldc + cA);
                v0.x += a0.x; v0.y += a0.y;
                v1.x += a1.x; v1.y += a1.y;
            }
            *(float2*)(C + (long)rA * ldc + cA) = v0;
            *(float2*)(C + (long)(rA + 8) * ldc + cA) = v1;
        }
    }
}

// ================= transpose =================
__global__ void transpose_kernel(const float* __restrict__ in, float* __restrict__ out,
                                 int rows, int cols)
{
    __shared__ float tile[32][33];
    int c = blockIdx.x * 32 + threadIdx.x;
    int r = blockIdx.y * 32 + threadIdx.y;
#pragma unroll
    for (int j = 0; j < 32; j += 8)
        tile[threadIdx.y + j][threadIdx.x] = in[(size_t)(r + j) * cols + c];
    __syncthreads();
    int c2 = blockIdx.y * 32 + threadIdx.x;
    int r2 = blockIdx.x * 32 + threadIdx.y;
#pragma unroll
    for (int j = 0; j < 32; j += 8)
        out[(size_t)(r2 + j) * rows + c2] = tile[threadIdx.x][threadIdx.y + j];
}

// ================= rmsnorm -> split bf16 (A-pattern hi|lo|hi) =================
__global__ void rmsnorm_split(const float* __restrict__ in, const float* __restrict__ w,
                              __nv_bfloat16* __restrict__ out, int N)
{
    size_t row = blockIdx.x;
    const float* p = in + row * N;
    __nv_bfloat16* o = out + row * 3L * N;
    int tid = threadIdx.x;
    float ss = 0.f;
    for (int i = tid * 4; i < N; i += 1024) {
        float4 v = *(const float4*)(p + i);
        ss += v.x * v.x + v.y * v.y + v.z * v.z + v.w * v.w;
    }
    __shared__ float red[8];
    for (int s = 16; s; s >>= 1) ss += __shfl_xor_sync(0xffffffffu, ss, s);
    if ((tid & 31) == 0) red[tid >> 5] = ss;
    __syncthreads();
    if (tid < 8) {
        float v = red[tid];
        for (int s = 4; s; s >>= 1) v += __shfl_xor_sync(0xffu, v, s);
        if (tid == 0) red[0] = v;
    }
    __syncthreads();
    float r = rsqrtf(red[0] / N + EPS);
    for (int i = tid * 2; i < N; i += 512) {
        float2 v = *(const float2*)(p + i);
        float2 wv = *(const float2*)(w + i);
        float y0 = v.x * r * wv.x, y1 = v.y * r * wv.y;
        __nv_bfloat16 h0, l0, h1, l1;
        split2(y0, h0, l0); split2(y1, h1, l1);
        __nv_bfloat162 th; th.x = h0; th.y = h1;
        __nv_bfloat162 tl; tl.x = l0; tl.y = l1;
        *(__nv_bfloat162*)(o + i) = th;
        *(__nv_bfloat162*)(o + N + i) = tl;
        *(__nv_bfloat162*)(o + 2L * N + i) = th;
    }
}

// ================= generic fp32 -> split bf16 (row-major) =================
__global__ void split_rm(const float* __restrict__ in, __nv_bfloat16* __restrict__ out,
                         int K, int isA)
{
    long r = blockIdx.x;
    int k = (blockIdx.y * 256 + threadIdx.x) * 2;
    float2 x = *(const float2*)(in + r * K + k);
    __nv_bfloat16 h0, l0, h1, l1;
    split2(x.x, h0, l0); split2(x.y, h1, l1);
    __nv_bfloat162 th; th.x = h0; th.y = h1;
    __nv_bfloat162 tl; tl.x = l0; tl.y = l1;
    __nv_bfloat16* o = out + r * 3L * K;
    *(__nv_bfloat162*)(o + k) = th;
    *(__nv_bfloat162*)(o + K + k) = isA ? tl : th;
    *(__nv_bfloat162*)(o + 2L * K + k) = isA ? th : tl;
}

// ================= per-(h,t) rmsnorm + RoPE -> split bf16, gathered [h][t][3*128] ===
__global__ void qknorm_rope_split(const float* __restrict__ qk, const float* __restrict__ w,
                                  const float* __restrict__ cosT, const float* __restrict__ sinT,
                                  __nv_bfloat16* __restrict__ out, int heads, int isA)
{
    int h = blockIdx.x, t = blockIdx.y, d = threadIdx.x;
    const float* p = qk + ((size_t)t * heads + h) * HD;
    float v = p[d];
    float ss = v * v;
    for (int s = 16; s; s >>= 1) ss += __shfl_xor_sync(0xffffffffu, ss, s);
    __shared__ float red[4];
    if ((d & 31) == 0) red[d >> 5] = ss;
    __syncthreads();
    float tot = red[0] + red[1] + red[2] + red[3];
    float r = rsqrtf(tot / HD + EPS);
    float xn = v * r * w[d];
    __shared__ float sv[HD];
    sv[d] = xn;
    __syncthreads();
    float rh = (d < HD / 2) ? -sv[d + HD / 2] : sv[d - HD / 2];
    float val = xn * cosT[(size_t)t * HD + d] + rh * sinT[(size_t)t * HD + d];
    __nv_bfloat16 hh, ll;
    split2(val, hh, ll);
    __nv_bfloat16* o = out + ((size_t)h * T2 + t) * (3 * HD);
    o[d] = hh;
    o[HD + d]     = isA ? ll : hh;
    o[2 * HD + d] = isA ? hh : ll;
}

// ================= V -> V^T split bf16 [h][d][3*T2] (B-pattern) =================
__global__ void split_vt(const float* __restrict__ v, __nv_bfloat16* __restrict__ out)
{
    int h = blockIdx.x;
    int d = blockIdx.y;
    __nv_bfloat16* o = out + ((size_t)h * HD + d) * (3 * T2);
    for (int s = threadIdx.x; s < T2; s += 256) {
        float x = v[((size_t)s * NKV + h) * HD + d];
        __nv_bfloat16 hh, ll;
        split2(x, hh, ll);
        o[s] = hh;
        o[T2 + s] = hh;
        o[2 * T2 + s] = ll;
    }
}

// ================= causal softmax -> split bf16 P (A-pattern) =================
__global__ void softmax_split(float* __restrict__ sc, __nv_bfloat16* __restrict__ pc)
{
    int i = blockIdx.x, h = blockIdx.y;
    float* row = sc + ((size_t)h * T2 + i) * T2;
    __nv_bfloat16* o = pc + ((size_t)h * T2 + i) * (3 * T2);
    int lim = i + 1;
    int tid = threadIdx.x;
    __shared__ float red[8];

    float m = -1e30f;
    for (int j = tid; j < lim; j += 256) m = fmaxf(m, row[j]);
    for (int s = 16; s; s >>= 1) m = fmaxf(m, __shfl_xor_sync(0xffffffffu, m, s));
    if ((tid & 31) == 0) red[tid >> 5] = m;
    __syncthreads();
    if (tid < 8) {
        float v = red[tid];
        for (int s = 4; s; s >>= 1) v = fmaxf(v, __shfl_xor_sync(0xffu, v, s));
        if (tid == 0) red[0] = v;
    }
    __syncthreads();
    float M = red[0];
    __syncthreads();

    float sum = 0.f;
    for (int j = tid; j < lim; j += 256) {
        float e = __expf((row[j] - M) * SCALE);
        row[j] = e;
        sum += e;
    }
    for (int s = 16; s; s >>= 1) sum += __shfl_xor_sync(0xffffffffu, sum, s);
    if ((tid & 31) == 0) red[tid >> 5] = sum;
    __syncthreads();
    if (tid < 8) {
        float v = red[tid];
        for (int s = 4; s; s >>= 1) v += __shfl_xor_sync(0xffu, v, s);
        if (tid == 0) red[0] = v;
    }
    __syncthreads();
    float inv = 1.f / red[0];
    __nv_bfloat16 z = __float2bfloat16_rn(0.f);
    for (int j = tid; j < lim; j += 256) {
        float p = row[j] * inv;
        __nv_bfloat16 hh, ll;
        split2(p, hh, ll);
        o[j] = hh; o[T2 + j] = ll; o[2 * T2 + j] = hh;
    }
    for (int j = lim + tid; j < T2; j += 256) {
        o[j] = z; o[T2 + j] = z; o[2 * T2 + j] = z;
    }
}

// ================= silu(gate)*up -> split bf16 (A-pattern) =================
__global__ void act_split(const float* __restrict__ gu, __nv_bfloat16* __restrict__ out)
{
    long t = blockIdx.x;
    int i = blockIdx.y * 256 + threadIdx.x;
    float g = gu[t * (2 * II) + i];
    float u = gu[t * (2 * II) + II + i];
    float a = g / (1.f + __expf(-g)) * u;
    __nv_bfloat16 hh, ll;
    split2(a, hh, ll);
    __nv_bfloat16* o = out + t * (3L * II);
    o[i] = hh; o[II + i] = ll; o[2L * II + i] = hh;
}

// ================= launch =================
extern "C" void kernel_launch(void* const* d_in, const int* in_sizes, int n_in,
                              void* d_out, int out_size)
{
    const float* hidden_conv = (const float*)d_in[0];
    const float* cosp = (const float*)d_in[1];
    const float* sinp = (const float*)d_in[2];
    const float* wq  = (const float*)d_in[5];
    const float* wk  = (const float*)d_in[6];
    const float* wv  = (const float*)d_in[7];
    const float* wo  = (const float*)d_in[8];
    const float* wgu = (const float*)d_in[9];
    const float* wd  = (const float*)d_in[10];
    const float* ilw = (const float*)d_in[11];
    const float* plw = (const float*)d_in[12];
    const float* qnw = (const float*)d_in[13];
    const float* knw = (const float*)d_in[14];
    float* out = (float*)d_out;

    float *px, *pq, *pk, *pv, *psc, *pao, *phid, *pgu, *ph2;
    __nv_bfloat16 *ch, *ch2, *cwq, *cwk, *cwv, *cwo, *cwgu, *cwd, *cact, *cq, *ck, *cvt, *cp, *cao;
    cudaGetSymbolAddress((void**)&px,   g_x);
    cudaGetSymbolAddress((void**)&pq,   g_q);
    cudaGetSymbolAddress((void**)&pk,   g_k);
    cudaGetSymbolAddress((void**)&pv,   g_v);
    cudaGetSymbolAddress((void**)&psc,  g_sc);
    cudaGetSymbolAddress((void**)&pao,  g_ao);
    cudaGetSymbolAddress((void**)&phid, g_hid);
    cudaGetSymbolAddress((void**)&pgu,  g_gu);
    cudaGetSymbolAddress((void**)&ph2,  g_h2);
    cudaGetSymbolAddress((void**)&ch,   c_h);
    cudaGetSymbolAddress((void**)&ch2,  c_h2);
    cudaGetSymbolAddress((void**)&cwq,  c_wq);
    cudaGetSymbolAddress((void**)&cwk,  c_wk);
    cudaGetSymbolAddress((void**)&cwv,  c_wv);
    cudaGetSymbolAddress((void**)&cwo,  c_wo);
    cudaGetSymbolAddress((void**)&cwgu, c_wgu);
    cudaGetSymbolAddress((void**)&cwd,  c_wd);
    cudaGetSymbolAddress((void**)&cact, c_act);
    cudaGetSymbolAddress((void**)&cq,   c_q);
    cudaGetSymbolAddress((void**)&ck,   c_k);
    cudaGetSymbolAddress((void**)&cvt,  c_vt);
    cudaGetSymbolAddress((void**)&cp,   c_p);
    cudaGetSymbolAddress((void**)&cao,  c_ao);

    const int SMEM_SZ = 6 * BUFB;   // 61440 B (3-stage A + B)
    cudaFuncSetAttribute(gemm_bf16, cudaFuncAttributeMaxDynamicSharedMemorySize, SMEM_SZ);

    dim3 tb(32, 8);

    // weight conversions (B-pattern)
    split_rm<<<dim3(2048, 4),  256>>>(wq,  cwq,  HIDN, 0);
    split_rm<<<dim3(1024, 4),  256>>>(wk,  cwk,  HIDN, 0);
    split_rm<<<dim3(1024, 4),  256>>>(wv,  cwv,  HIDN, 0);
    split_rm<<<dim3(2048, 4),  256>>>(wo,  cwo,  NH * HD, 0);
    split_rm<<<dim3(16384, 4), 256>>>(wgu, cwgu, HIDN, 0);
    split_rm<<<dim3(2048, 16), 256>>>(wd,  cwd,  II, 0);

    // x = hidden_conv[0,:,0,:].T ; h_cat = split(rms(x))
    transpose_kernel<<<dim3(T2 / 32, HIDN / 32), tb>>>(hidden_conv, px, HIDN, T2);
    rmsnorm_split<<<T2, 256>>>(px, ilw, ch, HIDN);

    // qkv projections (K' = 6144)
    gemm_bf16<<<dim3(16, 16, 1), 256, SMEM_SZ>>>(ch, cwq, nullptr, pq, 3 * HIDN, 3 * HIDN, 3 * HIDN, NH * HD, 0, 0, 0, 1, 0, 0);
    gemm_bf16<<<dim3(8, 16, 1),  256, SMEM_SZ>>>(ch, cwk, nullptr, pk, 3 * HIDN, 3 * HIDN, 3 * HIDN, NKV * HD, 0, 0, 0, 1, 0, 0);
    gemm_bf16<<<dim3(8, 16, 1),  256, SMEM_SZ>>>(ch, cwv, nullptr, pv, 3 * HIDN, 3 * HIDN, 3 * HIDN, NKV * HD, 0, 0, 0, 1, 0, 0);

    // q/k norm + rope + split-gather; v transpose-split
    qknorm_rope_split<<<dim3(NH, T2),  HD>>>(pq, qnw, cosp, sinp, cq, NH, 1);
    qknorm_rope_split<<<dim3(NKV, T2), HD>>>(pk, knw, cosp, sinp, ck, NKV, 0);
    split_vt<<<dim3(NKV, HD), 256>>>(pv, cvt);

    // scores[h] = Q_h * K_{h/2}^T  (K' = 384) — causal tile skip
    gemm_bf16<<<dim3(16, 16, NH), 256, SMEM_SZ>>>(cq, ck, nullptr, psc, 3 * HD, 3 * HD, 3 * HD, T2,
                                                  (long)T2 * 3 * HD, (long)T2 * 3 * HD, (long)T2 * T2, 2, 1, 0);

    // softmax + P split
    softmax_split<<<dim3(T2, NH), 256>>>(psc, cp);

    // attn_out[h] = P_h * V_{h/2}  (K' = 6144, N = 128) — segment-limited K (causal P)
    gemm_bf16<<<dim3(1, 16, NH), 256, SMEM_SZ>>>(cp, cvt, nullptr, pao, 3 * T2, 3 * T2, 3 * T2, NH * HD,
                                                 (long)T2 * 3 * T2, (long)HD * 3 * T2, (long)HD, 2, 0, T2 / 32);

    // ao split (A-pattern), then hidden = x + ao @ wo^T
    split_rm<<<dim3(2048, 4), 256>>>(pao, cao, NH * HD, 1);
    gemm_bf16<<<dim3(16, 16, 1), 256, SMEM_SZ>>>(cao, cwo, px, phid, 3 * NH * HD, 3 * NH * HD, 3 * NH * HD, HIDN, 0, 0, 0, 1, 0, 0);

    // h2_cat = split(rms(hidden)); gu = h2 @ wgu^T
    rmsnorm_split<<<T2, 256>>>(phid, plw, ch2, HIDN);
    gemm_bf16<<<dim3(128, 16, 1), 256, SMEM_SZ>>>(ch2, cwgu, nullptr, pgu, 3 * HIDN, 3 * HIDN, 3 * HIDN, 2 * II, 0, 0, 0, 1, 0, 0);

    // act = split(silu(gate)*up); final = hidden + act @ wd^T
    act_split<<<dim3(T2, II / 256), 256>>>(pgu, cact);
    gemm_bf16<<<dim3(16, 16, 1), 256, SMEM_SZ>>>(cact, cwd, phid, ph2, 3 * II, 3 * II, 3 * II, HIDN, 0, 0, 0, 1, 0, 0);

    // out = final.T
    transpose_kernel<<<dim3(HIDN / 32, T2 / 32), tb>>>(ph2, out, T2, HIDN);
}

// round 13
// speedup vs baseline: 1.0473x; 1.0473x over previous
#include <cuda_runtime.h>
#include <cuda_bf16.h>
#include <math.h>

#define T2   2048
#define HIDN 2048
#define NH   16
#define NKV  8
#define HD   128
#define II   8192
#define EPS  1e-6f
#define SCALE 0.08838834764831845f   // 1/sqrt(128)
#define PITCH 40                      // smem row pitch in bf16 (80B): ldmatrix/B-load conflict-free

// ================= scratch (static device globals; no allocations) =================
__device__ __align__(256) float g_x  [(size_t)T2 * HIDN];
__device__ __align__(256) float g_q  [(size_t)T2 * NH  * HD];
__device__ __align__(256) float g_k  [(size_t)T2 * NKV * HD];
__device__ __align__(256) float g_v  [(size_t)T2 * NKV * HD];
__device__ __align__(256) float g_sc [(size_t)NH * T2 * T2];
__device__ __align__(256) float g_ao [(size_t)T2 * NH * HD];
__device__ __align__(256) float g_hid[(size_t)T2 * HIDN];
__device__ __align__(256) float g_gu [(size_t)T2 * 2 * II];
__device__ __align__(256) float g_h2 [(size_t)T2 * HIDN];

// bf16 split-concat buffers (A-pattern: hi|lo|hi ; B-pattern: hi|hi|lo)
__device__ __align__(256) __nv_bfloat16 c_h  [(size_t)T2 * 3 * HIDN];
__device__ __align__(256) __nv_bfloat16 c_h2 [(size_t)T2 * 3 * HIDN];
__device__ __align__(256) __nv_bfloat16 c_wq [(size_t)(NH * HD) * 3 * HIDN];
__device__ __align__(256) __nv_bfloat16 c_wk [(size_t)(NKV * HD) * 3 * HIDN];
__device__ __align__(256) __nv_bfloat16 c_wv [(size_t)(NKV * HD) * 3 * HIDN];
__device__ __align__(256) __nv_bfloat16 c_wo [(size_t)HIDN * 3 * (NH * HD)];
__device__ __align__(256) __nv_bfloat16 c_wgu[(size_t)(2 * II) * 3 * HIDN];
__device__ __align__(256) __nv_bfloat16 c_wd [(size_t)HIDN * 3 * II];
__device__ __align__(256) __nv_bfloat16 c_act[(size_t)T2 * 3 * II];
__device__ __align__(256) __nv_bfloat16 c_q  [(size_t)NH  * T2 * 3 * HD];
__device__ __align__(256) __nv_bfloat16 c_k  [(size_t)NKV * T2 * 3 * HD];
__device__ __align__(256) __nv_bfloat16 c_vt [(size_t)NKV * HD * 3 * T2];
__device__ __align__(256) __nv_bfloat16 c_p  [(size_t)NH * T2 * 3 * T2];
__device__ __align__(256) __nv_bfloat16 c_ao [(size_t)T2 * 3 * (NH * HD)];

// ================= mma.sync helpers (baseline PTX — compiles for sm_103) =================
__device__ __forceinline__ unsigned smem_u32(const void* p) {
    unsigned a;
    asm("{ .reg .u64 t; cvta.to.shared.u64 t, %1; cvt.u32.u64 %0, t; }" : "=r"(a) : "l"(p));
    return a;
}
__device__ __forceinline__ void ldsm4(unsigned* r, unsigned addr) {
    asm volatile("ldmatrix.sync.aligned.m8n8.x4.shared.b16 {%0,%1,%2,%3}, [%4];"
                 : "=r"(r[0]), "=r"(r[1]), "=r"(r[2]), "=r"(r[3]) : "r"(addr));
}
__device__ __forceinline__ void mma16816(float* c, const unsigned* a, const unsigned* b) {
    asm volatile(
        "mma.sync.aligned.m16n8k16.row.col.f32.bf16.bf16.f32 "
        "{%0,%1,%2,%3}, {%4,%5,%6,%7}, {%8,%9}, {%0,%1,%2,%3};"
        : "+f"(c[0]), "+f"(c[1]), "+f"(c[2]), "+f"(c[3])
        : "r"(a[0]), "r"(a[1]), "r"(a[2]), "r"(a[3]), "r"(b[0]), "r"(b[1]));
}

__device__ __forceinline__ void split2(float x, __nv_bfloat16& h, __nv_bfloat16& l) {
    h = __float2bfloat16_rn(x);
    l = __float2bfloat16_rn(x - __bfloat162float(h));
}

// ================= split-bf16 GEMM via mma.sync (Round-9 engine) + causal skip =================
// C[M,N](fp32) = A[M,Kp](bf16) * B[N,Kp](bf16)^T (+ Add), 128x128 tiles, K chunks of 32.
// causal!=0: skip tile entirely when n0 > m0+127 (output never read there).
// seg_len>0: Kp = 3 segments of seg_len chunks; only first min(seg_len,(by+1)*4)
//            chunks of each segment are nonzero (causal P) -> iterate those only.
__global__ void __launch_bounds__(256) gemm_bf16(
    const __nv_bfloat16* __restrict__ A, const __nv_bfloat16* __restrict__ B,
    const float* __restrict__ Add, float* __restrict__ C,
    int Kp, int lda, int ldb, int ldc, long sA, long sB, long sC, int bdiv,
    int causal, int seg_len)
{
    const int m0 = blockIdx.y * 128;
    const int n0 = blockIdx.x * 128;
    if (causal && n0 > m0 + 127) return;

    __shared__ __nv_bfloat16 As[2][128][PITCH];
    __shared__ __nv_bfloat16 Bs[2][128][PITCH];

    const int tid  = threadIdx.x;
    const int lane = tid & 31;
    const int wid  = tid >> 5;
    const int wm   = (wid & 1) * 64;   // warp M offset within block tile
    const int wn   = (wid >> 1) * 32;  // warp N offset within block tile

    const int bz = blockIdx.z;
    A += (long)bz * sA;
    B += (long)(bz / bdiv) * sB;
    C += (long)bz * sC;
    if (Add) Add += (long)bz * sC;

    // global->smem mapping: 512 16B segments per chunk, 2 per thread
    const int lr0 = tid >> 2;            // rows 0..63
    const int lr1 = (tid >> 2) + 64;     // rows 64..127
    const int sg  = (tid & 3) * 8;       // col segment (bf16 elems)

    float acc[4][4][4];
#pragma unroll
    for (int i = 0; i < 4; i++)
#pragma unroll
        for (int j = 0; j < 4; j++)
#pragma unroll
            for (int e = 0; e < 4; e++) acc[i][j][e] = 0.f;

    const int nch   = Kp >> 5;
    const int valid = seg_len ? min(seg_len, ((int)blockIdx.y + 1) * 4) : 0;
    const int nit   = seg_len ? 3 * valid : nch;
    // logical iteration -> physical chunk index
    auto chunk_of = [&](int it) {
        return seg_len ? ((it / valid) * seg_len + (it % valid)) : it;
    };

    uint4 pa0, pa1, pb0, pb1;

    // preload logical chunk 0
    {
        const int k0 = chunk_of(0) * 32;
        pa0 = *(const uint4*)(A + (long)(m0 + lr0) * lda + k0 + sg);
        pa1 = *(const uint4*)(A + (long)(m0 + lr1) * lda + k0 + sg);
        pb0 = *(const uint4*)(B + (long)(n0 + lr0) * ldb + k0 + sg);
        pb1 = *(const uint4*)(B + (long)(n0 + lr1) * ldb + k0 + sg);
        *(uint4*)&As[0][lr0][sg] = pa0;
        *(uint4*)&As[0][lr1][sg] = pa1;
        *(uint4*)&Bs[0][lr0][sg] = pb0;
        *(uint4*)&Bs[0][lr1][sg] = pb1;
    }
    __syncthreads();

    for (int it = 0; it < nit; it++) {
        const int buf = it & 1;
        if (it + 1 < nit) {
            const int k0 = chunk_of(it + 1) * 32;
            pa0 = *(const uint4*)(A + (long)(m0 + lr0) * lda + k0 + sg);
            pa1 = *(const uint4*)(A + (long)(m0 + lr1) * lda + k0 + sg);
            pb0 = *(const uint4*)(B + (long)(n0 + lr0) * ldb + k0 + sg);
            pb1 = *(const uint4*)(B + (long)(n0 + lr1) * ldb + k0 + sg);
        }
#pragma unroll
        for (int kk = 0; kk < 32; kk += 16) {
            unsigned af[4][4];
#pragma unroll
            for (int mt = 0; mt < 4; mt++) {
                unsigned addr = smem_u32(&As[buf][wm + mt * 16 + (lane & 15)][kk + (lane >> 4) * 8]);
                ldsm4(af[mt], addr);
            }
            unsigned bfr[4][2];
#pragma unroll
            for (int nt = 0; nt < 4; nt++) {
                const __nv_bfloat16* bp = &Bs[buf][wn + nt * 8 + (lane >> 2)][kk + (lane & 3) * 2];
                bfr[nt][0] = *(const unsigned*)bp;
                bfr[nt][1] = *(const unsigned*)(bp + 8);
            }
#pragma unroll
            for (int mt = 0; mt < 4; mt++)
#pragma unroll
                for (int nt = 0; nt < 4; nt++)
                    mma16816(acc[mt][nt], af[mt], bfr[nt]);
        }
        __syncthreads();
        if (it + 1 < nit) {
            const int nb = buf ^ 1;
            *(uint4*)&As[nb][lr0][sg] = pa0;
            *(uint4*)&As[nb][lr1][sg] = pa1;
            *(uint4*)&Bs[nb][lr0][sg] = pb0;
            *(uint4*)&Bs[nb][lr1][sg] = pb1;
            __syncthreads();
        }
    }

    // epilogue: c0,c1 at (row, col..col+1); c2,c3 at (row+8, col..col+1)
    const int er = lane >> 2;
    const int ec = (lane & 3) * 2;
#pragma unroll
    for (int mt = 0; mt < 4; mt++) {
        const int rA = m0 + wm + mt * 16 + er;
#pragma unroll
        for (int nt = 0; nt < 4; nt++) {
            const int cA = n0 + wn + nt * 8 + ec;
            float2 v0 = make_float2(acc[mt][nt][0], acc[mt][nt][1]);
            float2 v1 = make_float2(acc[mt][nt][2], acc[mt][nt][3]);
            if (Add) {
                float2 a0 = *(const float2*)(Add + (long)rA * ldc + cA);
                float2 a1 = *(const float2*)(Add + (long)(rA + 8) * ldc + cA);
                v0.x += a0.x; v0.y += a0.y;
                v1.x += a1.x; v1.y += a1.y;
            }
            *(float2*)(C + (long)rA * ldc + cA) = v0;
            *(float2*)(C + (long)(rA + 8) * ldc + cA) = v1;
        }
    }
}

// ================= transpose =================
__global__ void transpose_kernel(const float* __restrict__ in, float* __restrict__ out,
                                 int rows, int cols)
{
    __shared__ float tile[32][33];
    int c = blockIdx.x * 32 + threadIdx.x;
    int r = blockIdx.y * 32 + threadIdx.y;
#pragma unroll
    for (int j = 0; j < 32; j += 8)
        tile[threadIdx.y + j][threadIdx.x] = in[(size_t)(r + j) * cols + c];
    __syncthreads();
    int c2 = blockIdx.y * 32 + threadIdx.x;
    int r2 = blockIdx.x * 32 + threadIdx.y;
#pragma unroll
    for (int j = 0; j < 32; j += 8)
        out[(size_t)(r2 + j) * rows + c2] = tile[threadIdx.x][threadIdx.y + j];
}

// ================= rmsnorm -> split bf16 (A-pattern hi|lo|hi) =================
__global__ void rmsnorm_split(const float* __restrict__ in, const float* __restrict__ w,
                              __nv_bfloat16* __restrict__ out, int N)
{
    size_t row = blockIdx.x;
    const float* p = in + row * N;
    __nv_bfloat16* o = out + row * 3L * N;
    int tid = threadIdx.x;
    float ss = 0.f;
    for (int i = tid * 4; i < N; i += 1024) {
        float4 v = *(const float4*)(p + i);
        ss += v.x * v.x + v.y * v.y + v.z * v.z + v.w * v.w;
    }
    __shared__ float red[8];
    for (int s = 16; s; s >>= 1) ss += __shfl_xor_sync(0xffffffffu, ss, s);
    if ((tid & 31) == 0) red[tid >> 5] = ss;
    __syncthreads();
    if (tid < 8) {
        float v = red[tid];
        for (int s = 4; s; s >>= 1) v += __shfl_xor_sync(0xffu, v, s);
        if (tid == 0) red[0] = v;
    }
    __syncthreads();
    float r = rsqrtf(red[0] / N + EPS);
    for (int i = tid * 2; i < N; i += 512) {
        float2 v = *(const float2*)(p + i);
        float2 wv = *(const float2*)(w + i);
        float y0 = v.x * r * wv.x, y1 = v.y * r * wv.y;
        __nv_bfloat16 h0, l0, h1, l1;
        split2(y0, h0, l0); split2(y1, h1, l1);
        __nv_bfloat162 th; th.x = h0; th.y = h1;
        __nv_bfloat162 tl; tl.x = l0; tl.y = l1;
        *(__nv_bfloat162*)(o + i) = th;
        *(__nv_bfloat162*)(o + N + i) = tl;
        *(__nv_bfloat162*)(o + 2L * N + i) = th;
    }
}

// ================= generic fp32 -> split bf16 (row-major) =================
__global__ void split_rm(const float* __restrict__ in, __nv_bfloat16* __restrict__ out,
                         int K, int isA)
{
    long r = blockIdx.x;
    int k = (blockIdx.y * 256 + threadIdx.x) * 2;
    float2 x = *(const float2*)(in + r * K + k);
    __nv_bfloat16 h0, l0, h1, l1;
    split2(x.x, h0, l0); split2(x.y, h1, l1);
    __nv_bfloat162 th; th.x = h0; th.y = h1;
    __nv_bfloat162 tl; tl.x = l0; tl.y = l1;
    __nv_bfloat16* o = out + r * 3L * K;
    *(__nv_bfloat162*)(o + k) = th;
    *(__nv_bfloat162*)(o + K + k) = isA ? tl : th;
    *(__nv_bfloat162*)(o + 2L * K + k) = isA ? th : tl;
}

// ================= per-(h,t) rmsnorm + RoPE -> split bf16, gathered [h][t][3*128] ===
__global__ void qknorm_rope_split(const float* __restrict__ qk, const float* __restrict__ w,
                                  const float* __restrict__ cosT, const float* __restrict__ sinT,
                                  __nv_bfloat16* __restrict__ out, int heads, int isA)
{
    int h = blockIdx.x, t = blockIdx.y, d = threadIdx.x;
    const float* p = qk + ((size_t)t * heads + h) * HD;
    float v = p[d];
    float ss = v * v;
    for (int s = 16; s; s >>= 1) ss += __shfl_xor_sync(0xffffffffu, ss, s);
    __shared__ float red[4];
    if ((d & 31) == 0) red[d >> 5] = ss;
    __syncthreads();
    float tot = red[0] + red[1] + red[2] + red[3];
    float r = rsqrtf(tot / HD + EPS);
    float xn = v * r * w[d];
    __shared__ float sv[HD];
    sv[d] = xn;
    __syncthreads();
    float rh = (d < HD / 2) ? -sv[d + HD / 2] : sv[d - HD / 2];
    float val = xn * cosT[(size_t)t * HD + d] + rh * sinT[(size_t)t * HD + d];
    __nv_bfloat16 hh, ll;
    split2(val, hh, ll);
    __nv_bfloat16* o = out + ((size_t)h * T2 + t) * (3 * HD);
    o[d] = hh;
    o[HD + d]     = isA ? ll : hh;
    o[2 * HD + d] = isA ? hh : ll;
}

// ================= V -> V^T split bf16 [h][d][3*T2] (B-pattern) =================
__global__ void split_vt(const float* __restrict__ v, __nv_bfloat16* __restrict__ out)
{
    int h = blockIdx.x;
    int d = blockIdx.y;
    __nv_bfloat16* o = out + ((size_t)h * HD + d) * (3 * T2);
    for (int s = threadIdx.x; s < T2; s += 256) {
        float x = v[((size_t)s * NKV + h) * HD + d];
        __nv_bfloat16 hh, ll;
        split2(x, hh, ll);
        o[s] = hh;
        o[T2 + s] = hh;
        o[2 * T2 + s] = ll;
    }
}

// ================= causal softmax -> split bf16 P (A-pattern) =================
__global__ void softmax_split(float* __restrict__ sc, __nv_bfloat16* __restrict__ pc)
{
    int i = blockIdx.x, h = blockIdx.y;
    float* row = sc + ((size_t)h * T2 + i) * T2;
    __nv_bfloat16* o = pc + ((size_t)h * T2 + i) * (3 * T2);
    int lim = i + 1;
    int tid = threadIdx.x;
    __shared__ float red[8];

    float m = -1e30f;
    for (int j = tid; j < lim; j += 256) m = fmaxf(m, row[j]);
    for (int s = 16; s; s >>= 1) m = fmaxf(m, __shfl_xor_sync(0xffffffffu, m, s));
    if ((tid & 31) == 0) red[tid >> 5] = m;
    __syncthreads();
    if (tid < 8) {
        float v = red[tid];
        for (int s = 4; s; s >>= 1) v = fmaxf(v, __shfl_xor_sync(0xffu, v, s));
        if (tid == 0) red[0] = v;
    }
    __syncthreads();
    float M = red[0];
    __syncthreads();

    float sum = 0.f;
    for (int j = tid; j < lim; j += 256) {
        float e = __expf((row[j] - M) * SCALE);
        row[j] = e;
        sum += e;
    }
    for (int s = 16; s; s >>= 1) sum += __shfl_xor_sync(0xffffffffu, sum, s);
    if ((tid & 31) == 0) red[tid >> 5] = sum;
    __syncthreads();
    if (tid < 8) {
        float v = red[tid];
        for (int s = 4; s; s >>= 1) v += __shfl_xor_sync(0xffu, v, s);
        if (tid == 0) red[0] = v;
    }
    __syncthreads();
    float inv = 1.f / red[0];
    __nv_bfloat16 z = __float2bfloat16_rn(0.f);
    for (int j = tid; j < lim; j += 256) {
        float p = row[j] * inv;
        __nv_bfloat16 hh, ll;
        split2(p, hh, ll);
        o[j] = hh; o[T2 + j] = ll; o[2 * T2 + j] = hh;
    }
    for (int j = lim + tid; j < T2; j += 256) {
        o[j] = z; o[T2 + j] = z; o[2 * T2 + j] = z;
    }
}

// ================= silu(gate)*up -> split bf16 (A-pattern) =================
__global__ void act_split(const float* __restrict__ gu, __nv_bfloat16* __restrict__ out)
{
    long t = blockIdx.x;
    int i = blockIdx.y * 256 + threadIdx.x;
    float g = gu[t * (2 * II) + i];
    float u = gu[t * (2 * II) + II + i];
    float a = g / (1.f + __expf(-g)) * u;
    __nv_bfloat16 hh, ll;
    split2(a, hh, ll);
    __nv_bfloat16* o = out + t * (3L * II);
    o[i] = hh; o[II + i] = ll; o[2L * II + i] = hh;
}

// ================= launch =================
extern "C" void kernel_launch(void* const* d_in, const int* in_sizes, int n_in,
                              void* d_out, int out_size)
{
    const float* hidden_conv = (const float*)d_in[0];
    const float* cosp = (const float*)d_in[1];
    const float* sinp = (const float*)d_in[2];
    const float* wq  = (const float*)d_in[5];
    const float* wk  = (const float*)d_in[6];
    const float* wv  = (const float*)d_in[7];
    const float* wo  = (const float*)d_in[8];
    const float* wgu = (const float*)d_in[9];
    const float* wd  = (const float*)d_in[10];
    const float* ilw = (const float*)d_in[11];
    const float* plw = (const float*)d_in[12];
    const float* qnw = (const float*)d_in[13];
    const float* knw = (const float*)d_in[14];
    float* out = (float*)d_out;

    float *px, *pq, *pk, *pv, *psc, *pao, *phid, *pgu, *ph2;
    __nv_bfloat16 *ch, *ch2, *cwq, *cwk, *cwv, *cwo, *cwgu, *cwd, *cact, *cq, *ck, *cvt, *cp, *cao;
    cudaGetSymbolAddress((void**)&px,   g_x);
    cudaGetSymbolAddress((void**)&pq,   g_q);
    cudaGetSymbolAddress((void**)&pk,   g_k);
    cudaGetSymbolAddress((void**)&pv,   g_v);
    cudaGetSymbolAddress((void**)&psc,  g_sc);
    cudaGetSymbolAddress((void**)&pao,  g_ao);
    cudaGetSymbolAddress((void**)&phid, g_hid);
    cudaGetSymbolAddress((void**)&pgu,  g_gu);
    cudaGetSymbolAddress((void**)&ph2,  g_h2);
    cudaGetSymbolAddress((void**)&ch,   c_h);
    cudaGetSymbolAddress((void**)&ch2,  c_h2);
    cudaGetSymbolAddress((void**)&cwq,  c_wq);
    cudaGetSymbolAddress((void**)&cwk,  c_wk);
    cudaGetSymbolAddress((void**)&cwv,  c_wv);
    cudaGetSymbolAddress((void**)&cwo,  c_wo);
    cudaGetSymbolAddress((void**)&cwgu, c_wgu);
    cudaGetSymbolAddress((void**)&cwd,  c_wd);
    cudaGetSymbolAddress((void**)&cact, c_act);
    cudaGetSymbolAddress((void**)&cq,   c_q);
    cudaGetSymbolAddress((void**)&ck,   c_k);
    cudaGetSymbolAddress((void**)&cvt,  c_vt);
    cudaGetSymbolAddress((void**)&cp,   c_p);
    cudaGetSymbolAddress((void**)&cao,  c_ao);

    dim3 tb(32, 8);

    // weight conversions (B-pattern)
    split_rm<<<dim3(2048, 4),  256>>>(wq,  cwq,  HIDN, 0);
    split_rm<<<dim3(1024, 4),  256>>>(wk,  cwk,  HIDN, 0);
    split_rm<<<dim3(1024, 4),  256>>>(wv,  cwv,  HIDN, 0);
    split_rm<<<dim3(2048, 4),  256>>>(wo,  cwo,  NH * HD, 0);
    split_rm<<<dim3(16384, 4), 256>>>(wgu, cwgu, HIDN, 0);
    split_rm<<<dim3(2048, 16), 256>>>(wd,  cwd,  II, 0);

    // x = hidden_conv[0,:,0,:].T ; h_cat = split(rms(x))
    transpose_kernel<<<dim3(T2 / 32, HIDN / 32), tb>>>(hidden_conv, px, HIDN, T2);
    rmsnorm_split<<<T2, 256>>>(px, ilw, ch, HIDN);

    // qkv projections (K' = 6144)
    gemm_bf16<<<dim3(16, 16, 1), 256>>>(ch, cwq, nullptr, pq, 3 * HIDN, 3 * HIDN, 3 * HIDN, NH * HD, 0, 0, 0, 1, 0, 0);
    gemm_bf16<<<dim3(8, 16, 1),  256>>>(ch, cwk, nullptr, pk, 3 * HIDN, 3 * HIDN, 3 * HIDN, NKV * HD, 0, 0, 0, 1, 0, 0);
    gemm_bf16<<<dim3(8, 16, 1),  256>>>(ch, cwv, nullptr, pv, 3 * HIDN, 3 * HIDN, 3 * HIDN, NKV * HD, 0, 0, 0, 1, 0, 0);

    // q/k norm + rope + split-gather; v transpose-split
    qknorm_rope_split<<<dim3(NH, T2),  HD>>>(pq, qnw, cosp, sinp, cq, NH, 1);
    qknorm_rope_split<<<dim3(NKV, T2), HD>>>(pk, knw, cosp, sinp, ck, NKV, 0);
    split_vt<<<dim3(NKV, HD), 256>>>(pv, cvt);

    // scores[h] = Q_h * K_{h/2}^T  (K' = 384) — causal tile skip
    gemm_bf16<<<dim3(16, 16, NH), 256>>>(cq, ck, nullptr, psc, 3 * HD, 3 * HD, 3 * HD, T2,
                                         (long)T2 * 3 * HD, (long)T2 * 3 * HD, (long)T2 * T2, 2, 1, 0);

    // softmax + P split
    softmax_split<<<dim3(T2, NH), 256>>>(psc, cp);

    // attn_out[h] = P_h * V_{h/2}  (K' = 6144, N = 128) — segment-limited K (causal P)
    gemm_bf16<<<dim3(1, 16, NH), 256>>>(cp, cvt, nullptr, pao, 3 * T2, 3 * T2, 3 * T2, NH * HD,
                                        (long)T2 * 3 * T2, (long)HD * 3 * T2, (long)HD, 2, 0, T2 / 32);

    // ao split (A-pattern), then hidden = x + ao @ wo^T
    split_rm<<<dim3(2048, 4), 256>>>(pao, cao, NH * HD, 1);
    gemm_bf16<<<dim3(16, 16, 1), 256>>>(cao, cwo, px, phid, 3 * NH * HD, 3 * NH * HD, 3 * NH * HD, HIDN, 0, 0, 0, 1, 0, 0);

    // h2_cat = split(rms(hidden)); gu = h2 @ wgu^T
    rmsnorm_split<<<T2, 256>>>(phid, plw, ch2, HIDN);
    gemm_bf16<<<dim3(128, 16, 1), 256>>>(ch2, cwgu, nullptr, pgu, 3 * HIDN, 3 * HIDN, 3 * HIDN, 2 * II, 0, 0, 0, 1, 0, 0);

    // act = split(silu(gate)*up); final = hidden + act @ wd^T
    act_split<<<dim3(T2, II / 256), 256>>>(pgu, cact);
    gemm_bf16<<<dim3(16, 16, 1), 256>>>(cact, cwd, phid, ph2, 3 * II, 3 * II, 3 * II, HIDN, 0, 0, 0, 1, 0, 0);

    // out = final.T
    transpose_kernel<<<dim3(HIDN / 32, T2 / 32), tb>>>(ph2, out, T2, HIDN);
}

// round 14
// speedup vs baseline: 1.1627x; 1.1102x over previous
#include <cuda_runtime.h>
#include <cuda_bf16.h>
#include <math.h>

#define T2   2048
#define HIDN 2048
#define NH   16
#define NKV  8
#define HD   128
#define II   8192
#define EPS  1e-6f
#define SCALE 0.08838834764831845f   // 1/sqrt(128)
#define PITCH 40                      // smem row pitch in bf16 (80B): ldmatrix conflict-free

// ================= scratch (static device globals; no allocations) =================
__device__ __align__(256) float g_x  [(size_t)T2 * HIDN];
__device__ __align__(256) float g_q  [(size_t)T2 * NH  * HD];
__device__ __align__(256) float g_k  [(size_t)T2 * NKV * HD];
__device__ __align__(256) float g_v  [(size_t)T2 * NKV * HD];
__device__ __align__(256) float g_sc [(size_t)NH * T2 * T2];
__device__ __align__(256) float g_ao [(size_t)T2 * NH * HD];
__device__ __align__(256) float g_hid[(size_t)T2 * HIDN];
__device__ __align__(256) float g_gu [(size_t)T2 * 2 * II];
__device__ __align__(256) float g_h2 [(size_t)T2 * HIDN];

// bf16 split-concat buffers (A-pattern: hi|lo|hi ; B-pattern: hi|hi|lo)
__device__ __align__(256) __nv_bfloat16 c_h  [(size_t)T2 * 3 * HIDN];
__device__ __align__(256) __nv_bfloat16 c_h2 [(size_t)T2 * 3 * HIDN];
__device__ __align__(256) __nv_bfloat16 c_wq [(size_t)(NH * HD) * 3 * HIDN];
__device__ __align__(256) __nv_bfloat16 c_wk [(size_t)(NKV * HD) * 3 * HIDN];
__device__ __align__(256) __nv_bfloat16 c_wv [(size_t)(NKV * HD) * 3 * HIDN];
__device__ __align__(256) __nv_bfloat16 c_wo [(size_t)HIDN * 3 * (NH * HD)];
__device__ __align__(256) __nv_bfloat16 c_wgu[(size_t)(2 * II) * 3 * HIDN];
__device__ __align__(256) __nv_bfloat16 c_wd [(size_t)HIDN * 3 * II];
__device__ __align__(256) __nv_bfloat16 c_act[(size_t)T2 * 3 * II];
__device__ __align__(256) __nv_bfloat16 c_q  [(size_t)NH  * T2 * 3 * HD];
__device__ __align__(256) __nv_bfloat16 c_k  [(size_t)NKV * T2 * 3 * HD];
__device__ __align__(256) __nv_bfloat16 c_vt [(size_t)NKV * HD * 3 * T2];
__device__ __align__(256) __nv_bfloat16 c_p  [(size_t)NH * T2 * 3 * T2];
__device__ __align__(256) __nv_bfloat16 c_ao [(size_t)T2 * 3 * (NH * HD)];

// ================= mma.sync helpers (baseline PTX — compiles for sm_103) =================
__device__ __forceinline__ unsigned smem_u32(const void* p) {
    unsigned a;
    asm("{ .reg .u64 t; cvta.to.shared.u64 t, %1; cvt.u32.u64 %0, t; }" : "=r"(a) : "l"(p));
    return a;
}
__device__ __forceinline__ void ldsm4(unsigned* r, unsigned addr) {
    asm volatile("ldmatrix.sync.aligned.m8n8.x4.shared.b16 {%0,%1,%2,%3}, [%4];"
                 : "=r"(r[0]), "=r"(r[1]), "=r"(r[2]), "=r"(r[3]) : "r"(addr));
}
__device__ __forceinline__ void mma16816(float* c, const unsigned* a, const unsigned* b) {
    asm volatile(
        "mma.sync.aligned.m16n8k16.row.col.f32.bf16.bf16.f32 "
        "{%0,%1,%2,%3}, {%4,%5,%6,%7}, {%8,%9}, {%0,%1,%2,%3};"
        : "+f"(c[0]), "+f"(c[1]), "+f"(c[2]), "+f"(c[3])
        : "r"(a[0]), "r"(a[1]), "r"(a[2]), "r"(a[3]), "r"(b[0]), "r"(b[1]));
}

__device__ __forceinline__ void split2(float x, __nv_bfloat16& h, __nv_bfloat16& l) {
    h = __float2bfloat16_rn(x);
    l = __float2bfloat16_rn(x - __bfloat162float(h));
}

// ================= split-bf16 GEMM via mma.sync + causal skip (ldmatrix A and B) =====
// C[M,N](fp32) = A[M,Kp](bf16) * B[N,Kp](bf16)^T (+ Add), 128x128 tiles, K chunks of 32.
// causal!=0: skip tile entirely when n0 > m0+127 (output never read there).
// seg_len>0: Kp = 3 segments of seg_len chunks; only first min(seg_len,(by+1)*4)
//            chunks of each segment are nonzero (causal P) -> iterate those only.
__global__ void __launch_bounds__(256) gemm_bf16(
    const __nv_bfloat16* __restrict__ A, const __nv_bfloat16* __restrict__ B,
    const float* __restrict__ Add, float* __restrict__ C,
    int Kp, int lda, int ldb, int ldc, long sA, long sB, long sC, int bdiv,
    int causal, int seg_len)
{
    const int m0 = blockIdx.y * 128;
    const int n0 = blockIdx.x * 128;
    if (causal && n0 > m0 + 127) return;

    __shared__ __nv_bfloat16 As[2][128][PITCH];
    __shared__ __nv_bfloat16 Bs[2][128][PITCH];

    const int tid  = threadIdx.x;
    const int lane = tid & 31;
    const int wid  = tid >> 5;
    const int wm   = (wid & 1) * 64;   // warp M offset within block tile
    const int wn   = (wid >> 1) * 32;  // warp N offset within block tile

    const int bz = blockIdx.z;
    A += (long)bz * sA;
    B += (long)(bz / bdiv) * sB;
    C += (long)bz * sC;
    if (Add) Add += (long)bz * sC;

    // global->smem mapping: 512 16B segments per chunk, 2 per thread
    const int lr0 = tid >> 2;            // rows 0..63
    const int lr1 = (tid >> 2) + 64;     // rows 64..127
    const int sg  = (tid & 3) * 8;       // col segment (bf16 elems)

    float acc[4][4][4];
#pragma unroll
    for (int i = 0; i < 4; i++)
#pragma unroll
        for (int j = 0; j < 4; j++)
#pragma unroll
            for (int e = 0; e < 4; e++) acc[i][j][e] = 0.f;

    const int nch   = Kp >> 5;
    const int valid = seg_len ? min(seg_len, ((int)blockIdx.y + 1) * 4) : 0;
    const int nit   = seg_len ? 3 * valid : nch;
    auto chunk_of = [&](int it) {
        return seg_len ? ((it / valid) * seg_len + (it % valid)) : it;
    };

    uint4 pa0, pa1, pb0, pb1;

    // preload logical chunk 0
    {
        const int k0 = chunk_of(0) * 32;
        pa0 = *(const uint4*)(A + (long)(m0 + lr0) * lda + k0 + sg);
        pa1 = *(const uint4*)(A + (long)(m0 + lr1) * lda + k0 + sg);
        pb0 = *(const uint4*)(B + (long)(n0 + lr0) * ldb + k0 + sg);
        pb1 = *(const uint4*)(B + (long)(n0 + lr1) * ldb + k0 + sg);
        *(uint4*)&As[0][lr0][sg] = pa0;
        *(uint4*)&As[0][lr1][sg] = pa1;
        *(uint4*)&Bs[0][lr0][sg] = pb0;
        *(uint4*)&Bs[0][lr1][sg] = pb1;
    }
    __syncthreads();

    // B-fragment ldmatrix lane mapping (x4: matrices {np2, klo},{np2, khi},{np2+1, klo},{np2+1, khi})
    const int br  = lane & 7;
    const int bs2 = lane >> 3;            // 0..3
    const int bnro = ((bs2 >> 1) * 8) + br;   // row offset within n16 group
    const int bko  = (bs2 & 1) * 8;           // k offset

    for (int it = 0; it < nit; it++) {
        const int buf = it & 1;
        if (it + 1 < nit) {
            const int k0 = chunk_of(it + 1) * 32;
            pa0 = *(const uint4*)(A + (long)(m0 + lr0) * lda + k0 + sg);
            pa1 = *(const uint4*)(A + (long)(m0 + lr1) * lda + k0 + sg);
            pb0 = *(const uint4*)(B + (long)(n0 + lr0) * ldb + k0 + sg);
            pb1 = *(const uint4*)(B + (long)(n0 + lr1) * ldb + k0 + sg);
        }
#pragma unroll
        for (int kk = 0; kk < 32; kk += 16) {
            unsigned af[4][4];
#pragma unroll
            for (int mt = 0; mt < 4; mt++) {
                unsigned addr = smem_u32(&As[buf][wm + mt * 16 + (lane & 15)][kk + (lane >> 4) * 8]);
                ldsm4(af[mt], addr);
            }
            unsigned bfr[4][2];
#pragma unroll
            for (int np = 0; np < 2; np++) {
                unsigned q[4];
                unsigned addr = smem_u32(&Bs[buf][wn + np * 16 + bnro][kk + bko]);
                ldsm4(q, addr);
                bfr[np * 2 + 0][0] = q[0]; bfr[np * 2 + 0][1] = q[1];
                bfr[np * 2 + 1][0] = q[2]; bfr[np * 2 + 1][1] = q[3];
            }
#pragma unroll
            for (int mt = 0; mt < 4; mt++)
#pragma unroll
                for (int nt = 0; nt < 4; nt++)
                    mma16816(acc[mt][nt], af[mt], bfr[nt]);
        }
        __syncthreads();
        if (it + 1 < nit) {
            const int nb = buf ^ 1;
            *(uint4*)&As[nb][lr0][sg] = pa0;
            *(uint4*)&As[nb][lr1][sg] = pa1;
            *(uint4*)&Bs[nb][lr0][sg] = pb0;
            *(uint4*)&Bs[nb][lr1][sg] = pb1;
            __syncthreads();
        }
    }

    // epilogue: c0,c1 at (row, col..col+1); c2,c3 at (row+8, col..col+1)
    const int er = lane >> 2;
    const int ec = (lane & 3) * 2;
#pragma unroll
    for (int mt = 0; mt < 4; mt++) {
        const int rA = m0 + wm + mt * 16 + er;
#pragma unroll
        for (int nt = 0; nt < 4; nt++) {
            const int cA = n0 + wn + nt * 8 + ec;
            float2 v0 = make_float2(acc[mt][nt][0], acc[mt][nt][1]);
            float2 v1 = make_float2(acc[mt][nt][2], acc[mt][nt][3]);
            if (Add) {
                float2 a0 = *(const float2*)(Add + (long)rA * ldc + cA);
                float2 a1 = *(const float2*)(Add + (long)(rA + 8) * ldc + cA);
                v0.x += a0.x; v0.y += a0.y;
                v1.x += a1.x; v1.y += a1.y;
            }
            *(float2*)(C + (long)rA * ldc + cA) = v0;
            *(float2*)(C + (long)(rA + 8) * ldc + cA) = v1;
        }
    }
}

// ================= transpose =================
__global__ void transpose_kernel(const float* __restrict__ in, float* __restrict__ out,
                                 int rows, int cols)
{
    __shared__ float tile[32][33];
    int c = blockIdx.x * 32 + threadIdx.x;
    int r = blockIdx.y * 32 + threadIdx.y;
#pragma unroll
    for (int j = 0; j < 32; j += 8)
        tile[threadIdx.y + j][threadIdx.x] = in[(size_t)(r + j) * cols + c];
    __syncthreads();
    int c2 = blockIdx.y * 32 + threadIdx.x;
    int r2 = blockIdx.x * 32 + threadIdx.y;
#pragma unroll
    for (int j = 0; j < 32; j += 8)
        out[(size_t)(r2 + j) * rows + c2] = tile[threadIdx.x][threadIdx.y + j];
}

// ================= rmsnorm -> split bf16 (A-pattern hi|lo|hi) =================
__global__ void rmsnorm_split(const float* __restrict__ in, const float* __restrict__ w,
                              __nv_bfloat16* __restrict__ out, int N)
{
    size_t row = blockIdx.x;
    const float* p = in + row * N;
    __nv_bfloat16* o = out + row * 3L * N;
    int tid = threadIdx.x;
    float ss = 0.f;
    for (int i = tid * 4; i < N; i += 1024) {
        float4 v = *(const float4*)(p + i);
        ss += v.x * v.x + v.y * v.y + v.z * v.z + v.w * v.w;
    }
    __shared__ float red[8];
    for (int s = 16; s; s >>= 1) ss += __shfl_xor_sync(0xffffffffu, ss, s);
    if ((tid & 31) == 0) red[tid >> 5] = ss;
    __syncthreads();
    if (tid < 8) {
        float v = red[tid];
        for (int s = 4; s; s >>= 1) v += __shfl_xor_sync(0xffu, v, s);
        if (tid == 0) red[0] = v;
    }
    __syncthreads();
    float r = rsqrtf(red[0] / N + EPS);
    for (int i = tid * 2; i < N; i += 512) {
        float2 v = *(const float2*)(p + i);
        float2 wv = *(const float2*)(w + i);
        float y0 = v.x * r * wv.x, y1 = v.y * r * wv.y;
        __nv_bfloat16 h0, l0, h1, l1;
        split2(y0, h0, l0); split2(y1, h1, l1);
        __nv_bfloat162 th; th.x = h0; th.y = h1;
        __nv_bfloat162 tl; tl.x = l0; tl.y = l1;
        *(__nv_bfloat162*)(o + i) = th;
        *(__nv_bfloat162*)(o + N + i) = tl;
        *(__nv_bfloat162*)(o + 2L * N + i) = th;
    }
}

// ================= generic fp32 -> split bf16 (row-major) =================
__global__ void split_rm(const float* __restrict__ in, __nv_bfloat16* __restrict__ out,
                         int K, int isA)
{
    long r = blockIdx.x;
    int k = (blockIdx.y * 256 + threadIdx.x) * 2;
    float2 x = *(const float2*)(in + r * K + k);
    __nv_bfloat16 h0, l0, h1, l1;
    split2(x.x, h0, l0); split2(x.y, h1, l1);
    __nv_bfloat162 th; th.x = h0; th.y = h1;
    __nv_bfloat162 tl; tl.x = l0; tl.y = l1;
    __nv_bfloat16* o = out + r * 3L * K;
    *(__nv_bfloat162*)(o + k) = th;
    *(__nv_bfloat162*)(o + K + k) = isA ? tl : th;
    *(__nv_bfloat162*)(o + 2L * K + k) = isA ? th : tl;
}

// ================= per-(h,t) rmsnorm + RoPE -> split bf16, gathered [h][t][3*128] ===
__global__ void qknorm_rope_split(const float* __restrict__ qk, const float* __restrict__ w,
                                  const float* __restrict__ cosT, const float* __restrict__ sinT,
                                  __nv_bfloat16* __restrict__ out, int heads, int isA)
{
    int h = blockIdx.x, t = blockIdx.y, d = threadIdx.x;
    const float* p = qk + ((size_t)t * heads + h) * HD;
    float v = p[d];
    float ss = v * v;
    for (int s = 16; s; s >>= 1) ss += __shfl_xor_sync(0xffffffffu, ss, s);
    __shared__ float red[4];
    if ((d & 31) == 0) red[d >> 5] = ss;
    __syncthreads();
    float tot = red[0] + red[1] + red[2] + red[3];
    float r = rsqrtf(tot / HD + EPS);
    float xn = v * r * w[d];
    __shared__ float sv[HD];
    sv[d] = xn;
    __syncthreads();
    float rh = (d < HD / 2) ? -sv[d + HD / 2] : sv[d - HD / 2];
    float val = xn * cosT[(size_t)t * HD + d] + rh * sinT[(size_t)t * HD + d];
    __nv_bfloat16 hh, ll;
    split2(val, hh, ll);
    __nv_bfloat16* o = out + ((size_t)h * T2 + t) * (3 * HD);
    o[d] = hh;
    o[HD + d]     = isA ? ll : hh;
    o[2 * HD + d] = isA ? hh : ll;
}

// ================= V -> V^T split bf16 [h][d][3*T2] (B-pattern) =================
__global__ void split_vt(const float* __restrict__ v, __nv_bfloat16* __restrict__ out)
{
    int h = blockIdx.x;
    int d = blockIdx.y;
    __nv_bfloat16* o = out + ((size_t)h * HD + d) * (3 * T2);
    for (int s = threadIdx.x; s < T2; s += 256) {
        float x = v[((size_t)s * NKV + h) * HD + d];
        __nv_bfloat16 hh, ll;
        split2(x, hh, ll);
        o[s] = hh;
        o[T2 + s] = hh;
        o[2 * T2 + s] = ll;
    }
}

// ================= causal softmax -> split bf16 P (A-pattern) =================
__global__ void softmax_split(float* __restrict__ sc, __nv_bfloat16* __restrict__ pc)
{
    int i = blockIdx.x, h = blockIdx.y;
    float* row = sc + ((size_t)h * T2 + i) * T2;
    __nv_bfloat16* o = pc + ((size_t)h * T2 + i) * (3 * T2);
    int lim = i + 1;
    int tid = threadIdx.x;
    __shared__ float red[8];

    float m = -1e30f;
    for (int j = tid; j < lim; j += 256) m = fmaxf(m, row[j]);
    for (int s = 16; s; s >>= 1) m = fmaxf(m, __shfl_xor_sync(0xffffffffu, m, s));
    if ((tid & 31) == 0) red[tid >> 5] = m;
    __syncthreads();
    if (tid < 8) {
        float v = red[tid];
        for (int s = 4; s; s >>= 1) v = fmaxf(v, __shfl_xor_sync(0xffu, v, s));
        if (tid == 0) red[0] = v;
    }
    __syncthreads();
    float M = red[0];
    __syncthreads();

    float sum = 0.f;
    for (int j = tid; j < lim; j += 256) {
        float e = __expf((row[j] - M) * SCALE);
        row[j] = e;
        sum += e;
    }
    for (int s = 16; s; s >>= 1) sum += __shfl_xor_sync(0xffffffffu, sum, s);
    if ((tid & 31) == 0) red[tid >> 5] = sum;
    __syncthreads();
    if (tid < 8) {
        float v = red[tid];
        for (int s = 4; s; s >>= 1) v += __shfl_xor_sync(0xffu, v, s);
        if (tid == 0) red[0] = v;
    }
    __syncthreads();
    float inv = 1.f / red[0];
    __nv_bfloat16 z = __float2bfloat16_rn(0.f);
    for (int j = tid; j < lim; j += 256) {
        float p = row[j] * inv;
        __nv_bfloat16 hh, ll;
        split2(p, hh, ll);
        o[j] = hh; o[T2 + j] = ll; o[2 * T2 + j] = hh;
    }
    for (int j = lim + tid; j < T2; j += 256) {
        o[j] = z; o[T2 + j] = z; o[2 * T2 + j] = z;
    }
}

// ================= silu(gate)*up -> split bf16 (A-pattern) =================
__global__ void act_split(const float* __restrict__ gu, __nv_bfloat16* __restrict__ out)
{
    long t = blockIdx.x;
    int i = blockIdx.y * 256 + threadIdx.x;
    float g = gu[t * (2 * II) + i];
    float u = gu[t * (2 * II) + II + i];
    float a = g / (1.f + __expf(-g)) * u;
    __nv_bfloat16 hh, ll;
    split2(a, hh, ll);
    __nv_bfloat16* o = out + t * (3L * II);
    o[i] = hh; o[II + i] = ll; o[2L * II + i] = hh;
}

// ================= launch =================
extern "C" void kernel_launch(void* const* d_in, const int* in_sizes, int n_in,
                              void* d_out, int out_size)
{
    const float* hidden_conv = (const float*)d_in[0];
    const float* cosp = (const float*)d_in[1];
    const float* sinp = (const float*)d_in[2];
    const float* wq  = (const float*)d_in[5];
    const float* wk  = (const float*)d_in[6];
    const float* wv  = (const float*)d_in[7];
    const float* wo  = (const float*)d_in[8];
    const float* wgu = (const float*)d_in[9];
    const float* wd  = (const float*)d_in[10];
    const float* ilw = (const float*)d_in[11];
    const float* plw = (const float*)d_in[12];
    const float* qnw = (const float*)d_in[13];
    const float* knw = (const float*)d_in[14];
    float* out = (float*)d_out;

    float *px, *pq, *pk, *pv, *psc, *pao, *phid, *pgu, *ph2;
    __nv_bfloat16 *ch, *ch2, *cwq, *cwk, *cwv, *cwo, *cwgu, *cwd, *cact, *cq, *ck, *cvt, *cp, *cao;
    cudaGetSymbolAddress((void**)&px,   g_x);
    cudaGetSymbolAddress((void**)&pq,   g_q);
    cudaGetSymbolAddress((void**)&pk,   g_k);
    cudaGetSymbolAddress((void**)&pv,   g_v);
    cudaGetSymbolAddress((void**)&psc,  g_sc);
    cudaGetSymbolAddress((void**)&pao,  g_ao);
    cudaGetSymbolAddress((void**)&phid, g_hid);
    cudaGetSymbolAddress((void**)&pgu,  g_gu);
    cudaGetSymbolAddress((void**)&ph2,  g_h2);
    cudaGetSymbolAddress((void**)&ch,   c_h);
    cudaGetSymbolAddress((void**)&ch2,  c_h2);
    cudaGetSymbolAddress((void**)&cwq,  c_wq);
    cudaGetSymbolAddress((void**)&cwk,  c_wk);
    cudaGetSymbolAddress((void**)&cwv,  c_wv);
    cudaGetSymbolAddress((void**)&cwo,  c_wo);
    cudaGetSymbolAddress((void**)&cwgu, c_wgu);
    cudaGetSymbolAddress((void**)&cwd,  c_wd);
    cudaGetSymbolAddress((void**)&cact, c_act);
    cudaGetSymbolAddress((void**)&cq,   c_q);
    cudaGetSymbolAddress((void**)&ck,   c_k);
    cudaGetSymbolAddress((void**)&cvt,  c_vt);
    cudaGetSymbolAddress((void**)&cp,   c_p);
    cudaGetSymbolAddress((void**)&cao,  c_ao);

    dim3 tb(32, 8);

    // Launch order arranged so launch index 5 (ncu -s 5 -c 1) is the big QKV GEMM.
    // 0-2: qkv weight splits; 3: transpose; 4: rmsnorm; 5: gemm(Q) <- profiled
    split_rm<<<dim3(2048, 4),  256>>>(wq,  cwq,  HIDN, 0);
    split_rm<<<dim3(1024, 4),  256>>>(wk,  cwk,  HIDN, 0);
    split_rm<<<dim3(1024, 4),  256>>>(wv,  cwv,  HIDN, 0);
    transpose_kernel<<<dim3(T2 / 32, HIDN / 32), tb>>>(hidden_conv, px, HIDN, T2);
    rmsnorm_split<<<T2, 256>>>(px, ilw, ch, HIDN);

    // qkv projections (K' = 6144)
    gemm_bf16<<<dim3(16, 16, 1), 256>>>(ch, cwq, nullptr, pq, 3 * HIDN, 3 * HIDN, 3 * HIDN, NH * HD, 0, 0, 0, 1, 0, 0);
    gemm_bf16<<<dim3(8, 16, 1),  256>>>(ch, cwk, nullptr, pk, 3 * HIDN, 3 * HIDN, 3 * HIDN, NKV * HD, 0, 0, 0, 1, 0, 0);
    gemm_bf16<<<dim3(8, 16, 1),  256>>>(ch, cwv, nullptr, pv, 3 * HIDN, 3 * HIDN, 3 * HIDN, NKV * HD, 0, 0, 0, 1, 0, 0);

    // q/k norm + rope + split-gather; v transpose-split
    qknorm_rope_split<<<dim3(NH, T2),  HD>>>(pq, qnw, cosp, sinp, cq, NH, 1);
    qknorm_rope_split<<<dim3(NKV, T2), HD>>>(pk, knw, cosp, sinp, ck, NKV, 0);
    split_vt<<<dim3(NKV, HD), 256>>>(pv, cvt);

    // scores[h] = Q_h * K_{h/2}^T  (K' = 384) — causal tile skip
    gemm_bf16<<<dim3(16, 16, NH), 256>>>(cq, ck, nullptr, psc, 3 * HD, 3 * HD, 3 * HD, T2,
                                         (long)T2 * 3 * HD, (long)T2 * 3 * HD, (long)T2 * T2, 2, 1, 0);

    // softmax + P split
    softmax_split<<<dim3(T2, NH), 256>>>(psc, cp);

    // attn_out[h] = P_h * V_{h/2}  (K' = 6144, N = 128) — segment-limited K (causal P)
    gemm_bf16<<<dim3(1, 16, NH), 256>>>(cp, cvt, nullptr, pao, 3 * T2, 3 * T2, 3 * T2, NH * HD,
                                        (long)T2 * 3 * T2, (long)HD * 3 * T2, (long)HD, 2, 0, T2 / 32);

    // wo split + ao split (A-pattern), then hidden = x + ao @ wo^T
    split_rm<<<dim3(2048, 4), 256>>>(wo, cwo, NH * HD, 0);
    split_rm<<<dim3(2048, 4), 256>>>(pao, cao, NH * HD, 1);
    gemm_bf16<<<dim3(16, 16, 1), 256>>>(cao, cwo, px, phid, 3 * NH * HD, 3 * NH * HD, 3 * NH * HD, HIDN, 0, 0, 0, 1, 0, 0);

    // h2_cat = split(rms(hidden)); gu = h2 @ wgu^T
    split_rm<<<dim3(16384, 4), 256>>>(wgu, cwgu, HIDN, 0);
    rmsnorm_split<<<T2, 256>>>(phid, plw, ch2, HIDN);
    gemm_bf16<<<dim3(128, 16, 1), 256>>>(ch2, cwgu, nullptr, pgu, 3 * HIDN, 3 * HIDN, 3 * HIDN, 2 * II, 0, 0, 0, 1, 0, 0);

    // act = split(silu(gate)*up); final = hidden + act @ wd^T
    split_rm<<<dim3(2048, 16), 256>>>(wd, cwd, II, 0);
    act_split<<<dim3(T2, II / 256), 256>>>(pgu, cact);
    gemm_bf16<<<dim3(16, 16, 1), 256>>>(cact, cwd, phid, ph2, 3 * II, 3 * II, 3 * II, HIDN, 0, 0, 0, 1, 0, 0);

    // out = final.T
    transpose_kernel<<<dim3(HIDN / 32, T2 / 32), tb>>>(ph2, out, T2, HIDN);
}

// round 15
// speedup vs baseline: 1.1669x; 1.0036x over previous
#include <cuda_runtime.h>
#include <cuda_bf16.h>
#include <math.h>

#define T2   2048
#define HIDN 2048
#define NH   16
#define NKV  8
#define HD   128
#define II   8192
#define EPS  1e-6f
#define SCALE 0.08838834764831845f   // 1/sqrt(128)
#define PITCH 40                      // smem row pitch in bf16 (80B): ldmatrix conflict-free

// ================= scratch (static device globals; no allocations) =================
__device__ __align__(256) float g_x  [(size_t)T2 * HIDN];
__device__ __align__(256) float g_q  [(size_t)T2 * NH  * HD];
__device__ __align__(256) float g_k  [(size_t)T2 * NKV * HD];
__device__ __align__(256) float g_v  [(size_t)T2 * NKV * HD];
__device__ __align__(256) float g_sc [(size_t)NH * T2 * T2];
__device__ __align__(256) float g_ao [(size_t)T2 * NH * HD];
__device__ __align__(256) float g_hid[(size_t)T2 * HIDN];
__device__ __align__(256) float g_gu [(size_t)T2 * 2 * II];
__device__ __align__(256) float g_h2 [(size_t)T2 * HIDN];

// bf16 split-concat buffers (A-pattern: hi|lo|hi ; B-pattern: hi|hi|lo)
__device__ __align__(256) __nv_bfloat16 c_h  [(size_t)T2 * 3 * HIDN];
__device__ __align__(256) __nv_bfloat16 c_h2 [(size_t)T2 * 3 * HIDN];
__device__ __align__(256) __nv_bfloat16 c_wq [(size_t)(NH * HD) * 3 * HIDN];
__device__ __align__(256) __nv_bfloat16 c_wk [(size_t)(NKV * HD) * 3 * HIDN];
__device__ __align__(256) __nv_bfloat16 c_wv [(size_t)(NKV * HD) * 3 * HIDN];
__device__ __align__(256) __nv_bfloat16 c_wo [(size_t)HIDN * 3 * (NH * HD)];
__device__ __align__(256) __nv_bfloat16 c_wgu[(size_t)(2 * II) * 3 * HIDN];
__device__ __align__(256) __nv_bfloat16 c_wd [(size_t)HIDN * 3 * II];
__device__ __align__(256) __nv_bfloat16 c_act[(size_t)T2 * 3 * II];
__device__ __align__(256) __nv_bfloat16 c_q  [(size_t)NH  * T2 * 3 * HD];
__device__ __align__(256) __nv_bfloat16 c_k  [(size_t)NKV * T2 * 3 * HD];
__device__ __align__(256) __nv_bfloat16 c_vt [(size_t)NKV * HD * 3 * T2];
__device__ __align__(256) __nv_bfloat16 c_p  [(size_t)NH * T2 * 3 * T2];
__device__ __align__(256) __nv_bfloat16 c_ao [(size_t)T2 * 3 * (NH * HD)];

// ================= mma.sync helpers (baseline PTX — compiles for sm_103) =================
__device__ __forceinline__ unsigned smem_u32(const void* p) {
    unsigned a;
    asm("{ .reg .u64 t; cvta.to.shared.u64 t, %1; cvt.u32.u64 %0, t; }" : "=r"(a) : "l"(p));
    return a;
}
__device__ __forceinline__ void ldsm4(unsigned* r, unsigned addr) {
    asm volatile("ldmatrix.sync.aligned.m8n8.x4.shared.b16 {%0,%1,%2,%3}, [%4];"
                 : "=r"(r[0]), "=r"(r[1]), "=r"(r[2]), "=r"(r[3]) : "r"(addr));
}
__device__ __forceinline__ void mma16816(float* c, const unsigned* a, const unsigned* b) {
    asm volatile(
        "mma.sync.aligned.m16n8k16.row.col.f32.bf16.bf16.f32 "
        "{%0,%1,%2,%3}, {%4,%5,%6,%7}, {%8,%9}, {%0,%1,%2,%3};"
        : "+f"(c[0]), "+f"(c[1]), "+f"(c[2]), "+f"(c[3])
        : "r"(a[0]), "r"(a[1]), "r"(a[2]), "r"(a[3]), "r"(b[0]), "r"(b[1]));
}

__device__ __forceinline__ void split2(float x, __nv_bfloat16& h, __nv_bfloat16& l) {
    h = __float2bfloat16_rn(x);
    l = __float2bfloat16_rn(x - __bfloat162float(h));
}

// ================= split-bf16 GEMM via mma.sync + causal skip (ldmatrix A and B) =====
// Grid mapping: blockIdx.x = M tile (fastest -> L2 reuse of B across m-tiles),
//               blockIdx.y = N tile, blockIdx.z = batch.
// C[M,N](fp32) = A[M,Kp](bf16) * B[N,Kp](bf16)^T (+ Add), 128x128 tiles, K chunks of 32.
// causal!=0: skip tile entirely when n0 > m0+127.
// seg_len>0: Kp = 3 segments of seg_len chunks; only first min(seg_len,(mtile+1)*4)
//            chunks of each segment are nonzero (causal P) -> iterate those only.
__global__ void __launch_bounds__(256) gemm_bf16(
    const __nv_bfloat16* __restrict__ A, const __nv_bfloat16* __restrict__ B,
    const float* __restrict__ Add, float* __restrict__ C,
    int Kp, int lda, int ldb, int ldc, long sA, long sB, long sC, int bdiv,
    int causal, int seg_len)
{
    const int m0 = blockIdx.x * 128;
    const int n0 = blockIdx.y * 128;
    if (causal && n0 > m0 + 127) return;

    __shared__ __nv_bfloat16 As[2][128][PITCH];
    __shared__ __nv_bfloat16 Bs[2][128][PITCH];

    const int tid  = threadIdx.x;
    const int lane = tid & 31;
    const int wid  = tid >> 5;
    const int wm   = (wid & 1) * 64;   // warp M offset within block tile
    const int wn   = (wid >> 1) * 32;  // warp N offset within block tile

    const int bz = blockIdx.z;
    A += (long)bz * sA;
    B += (long)(bz / bdiv) * sB;
    C += (long)bz * sC;
    if (Add) Add += (long)bz * sC;

    // global->smem mapping: 512 16B segments per chunk, 2 per thread
    const int lr0 = tid >> 2;            // rows 0..63
    const int lr1 = (tid >> 2) + 64;     // rows 64..127
    const int sg  = (tid & 3) * 8;       // col segment (bf16 elems)

    float acc[4][4][4];
#pragma unroll
    for (int i = 0; i < 4; i++)
#pragma unroll
        for (int j = 0; j < 4; j++)
#pragma unroll
            for (int e = 0; e < 4; e++) acc[i][j][e] = 0.f;

    const int nch   = Kp >> 5;
    const int valid = seg_len ? min(seg_len, ((int)blockIdx.x + 1) * 4) : 0;
    const int nit   = seg_len ? 3 * valid : nch;
    auto chunk_of = [&](int it) {
        return seg_len ? ((it / valid) * seg_len + (it % valid)) : it;
    };

    uint4 pa0, pa1, pb0, pb1;

    // preload logical chunk 0
    {
        const int k0 = chunk_of(0) * 32;
        pa0 = *(const uint4*)(A + (long)(m0 + lr0) * lda + k0 + sg);
        pa1 = *(const uint4*)(A + (long)(m0 + lr1) * lda + k0 + sg);
        pb0 = *(const uint4*)(B + (long)(n0 + lr0) * ldb + k0 + sg);
        pb1 = *(const uint4*)(B + (long)(n0 + lr1) * ldb + k0 + sg);
        *(uint4*)&As[0][lr0][sg] = pa0;
        *(uint4*)&As[0][lr1][sg] = pa1;
        *(uint4*)&Bs[0][lr0][sg] = pb0;
        *(uint4*)&Bs[0][lr1][sg] = pb1;
    }
    __syncthreads();

    // B-fragment ldmatrix lane mapping (x4: matrices {np2, klo},{np2, khi},{np2+1, klo},{np2+1, khi})
    const int br  = lane & 7;
    const int bs2 = lane >> 3;            // 0..3
    const int bnro = ((bs2 >> 1) * 8) + br;   // row offset within n16 group
    const int bko  = (bs2 & 1) * 8;           // k offset

    for (int it = 0; it < nit; it++) {
        const int buf = it & 1;
        if (it + 1 < nit) {
            const int k0 = chunk_of(it + 1) * 32;
            pa0 = *(const uint4*)(A + (long)(m0 + lr0) * lda + k0 + sg);
            pa1 = *(const uint4*)(A + (long)(m0 + lr1) * lda + k0 + sg);
            pb0 = *(const uint4*)(B + (long)(n0 + lr0) * ldb + k0 + sg);
            pb1 = *(const uint4*)(B + (long)(n0 + lr1) * ldb + k0 + sg);
        }
#pragma unroll
        for (int kk = 0; kk < 32; kk += 16) {
            unsigned af[4][4];
#pragma unroll
            for (int mt = 0; mt < 4; mt++) {
                unsigned addr = smem_u32(&As[buf][wm + mt * 16 + (lane & 15)][kk + (lane >> 4) * 8]);
                ldsm4(af[mt], addr);
            }
            unsigned bfr[4][2];
#pragma unroll
            for (int np = 0; np < 2; np++) {
                unsigned q[4];
                unsigned addr = smem_u32(&Bs[buf][wn + np * 16 + bnro][kk + bko]);
                ldsm4(q, addr);
                bfr[np * 2 + 0][0] = q[0]; bfr[np * 2 + 0][1] = q[1];
                bfr[np * 2 + 1][0] = q[2]; bfr[np * 2 + 1][1] = q[3];
            }
#pragma unroll
            for (int mt = 0; mt < 4; mt++)
#pragma unroll
                for (int nt = 0; nt < 4; nt++)
                    mma16816(acc[mt][nt], af[mt], bfr[nt]);
        }
        __syncthreads();
        if (it + 1 < nit) {
            const int nb = buf ^ 1;
            *(uint4*)&As[nb][lr0][sg] = pa0;
            *(uint4*)&As[nb][lr1][sg] = pa1;
            *(uint4*)&Bs[nb][lr0][sg] = pb0;
            *(uint4*)&Bs[nb][lr1][sg] = pb1;
            __syncthreads();
        }
    }

    // epilogue: c0,c1 at (row, col..col+1); c2,c3 at (row+8, col..col+1)
    const int er = lane >> 2;
    const int ec = (lane & 3) * 2;
#pragma unroll
    for (int mt = 0; mt < 4; mt++) {
        const int rA = m0 + wm + mt * 16 + er;
#pragma unroll
        for (int nt = 0; nt < 4; nt++) {
            const int cA = n0 + wn + nt * 8 + ec;
            float2 v0 = make_float2(acc[mt][nt][0], acc[mt][nt][1]);
            float2 v1 = make_float2(acc[mt][nt][2], acc[mt][nt][3]);
            if (Add) {
                float2 a0 = *(const float2*)(Add + (long)rA * ldc + cA);
                float2 a1 = *(const float2*)(Add + (long)(rA + 8) * ldc + cA);
                v0.x += a0.x; v0.y += a0.y;
                v1.x += a1.x; v1.y += a1.y;
            }
            *(float2*)(C + (long)rA * ldc + cA) = v0;
            *(float2*)(C + (long)(rA + 8) * ldc + cA) = v1;
        }
    }
}

// ================= transpose =================
__global__ void transpose_kernel(const float* __restrict__ in, float* __restrict__ out,
                                 int rows, int cols)
{
    __shared__ float tile[32][33];
    int c = blockIdx.x * 32 + threadIdx.x;
    int r = blockIdx.y * 32 + threadIdx.y;
#pragma unroll
    for (int j = 0; j < 32; j += 8)
        tile[threadIdx.y + j][threadIdx.x] = in[(size_t)(r + j) * cols + c];
    __syncthreads();
    int c2 = blockIdx.y * 32 + threadIdx.x;
    int r2 = blockIdx.x * 32 + threadIdx.y;
#pragma unroll
    for (int j = 0; j < 32; j += 8)
        out[(size_t)(r2 + j) * rows + c2] = tile[threadIdx.x][threadIdx.y + j];
}

// ================= rmsnorm -> split bf16 (A-pattern hi|lo|hi) =================
__global__ void rmsnorm_split(const float* __restrict__ in, const float* __restrict__ w,
                              __nv_bfloat16* __restrict__ out, int N)
{
    size_t row = blockIdx.x;
    const float* p = in + row * N;
    __nv_bfloat16* o = out + row * 3L * N;
    int tid = threadIdx.x;
    float ss = 0.f;
    for (int i = tid * 4; i < N; i += 1024) {
        float4 v = *(const float4*)(p + i);
        ss += v.x * v.x + v.y * v.y + v.z * v.z + v.w * v.w;
    }
    __shared__ float red[8];
    for (int s = 16; s; s >>= 1) ss += __shfl_xor_sync(0xffffffffu, ss, s);
    if ((tid & 31) == 0) red[tid >> 5] = ss;
    __syncthreads();
    if (tid < 8) {
        float v = red[tid];
        for (int s = 4; s; s >>= 1) v += __shfl_xor_sync(0xffu, v, s);
        if (tid == 0) red[0] = v;
    }
    __syncthreads();
    float r = rsqrtf(red[0] / N + EPS);
    for (int i = tid * 2; i < N; i += 512) {
        float2 v = *(const float2*)(p + i);
        float2 wv = *(const float2*)(w + i);
        float y0 = v.x * r * wv.x, y1 = v.y * r * wv.y;
        __nv_bfloat16 h0, l0, h1, l1;
        split2(y0, h0, l0); split2(y1, h1, l1);
        __nv_bfloat162 th; th.x = h0; th.y = h1;
        __nv_bfloat162 tl; tl.x = l0; tl.y = l1;
        *(__nv_bfloat162*)(o + i) = th;
        *(__nv_bfloat162*)(o + N + i) = tl;
        *(__nv_bfloat162*)(o + 2L * N + i) = th;
    }
}

// ================= generic fp32 -> split bf16 (row-major) =================
__global__ void split_rm(const float* __restrict__ in, __nv_bfloat16* __restrict__ out,
                         int K, int isA)
{
    long r = blockIdx.x;
    int k = (blockIdx.y * 256 + threadIdx.x) * 2;
    float2 x = *(const float2*)(in + r * K + k);
    __nv_bfloat16 h0, l0, h1, l1;
    split2(x.x, h0, l0); split2(x.y, h1, l1);
    __nv_bfloat162 th; th.x = h0; th.y = h1;
    __nv_bfloat162 tl; tl.x = l0; tl.y = l1;
    __nv_bfloat16* o = out + r * 3L * K;
    *(__nv_bfloat162*)(o + k) = th;
    *(__nv_bfloat162*)(o + K + k) = isA ? tl : th;
    *(__nv_bfloat162*)(o + 2L * K + k) = isA ? th : tl;
}

// ================= per-(h,t) rmsnorm + RoPE -> split bf16, gathered [h][t][3*128] ===
__global__ void qknorm_rope_split(const float* __restrict__ qk, const float* __restrict__ w,
                                  const float* __restrict__ cosT, const float* __restrict__ sinT,
                                  __nv_bfloat16* __restrict__ out, int heads, int isA)
{
    int h = blockIdx.x, t = blockIdx.y, d = threadIdx.x;
    const float* p = qk + ((size_t)t * heads + h) * HD;
    float v = p[d];
    float ss = v * v;
    for (int s = 16; s; s >>= 1) ss += __shfl_xor_sync(0xffffffffu, ss, s);
    __shared__ float red[4];
    if ((d & 31) == 0) red[d >> 5] = ss;
    __syncthreads();
    float tot = red[0] + red[1] + red[2] + red[3];
    float r = rsqrtf(tot / HD + EPS);
    float xn = v * r * w[d];
    __shared__ float sv[HD];
    sv[d] = xn;
    __syncthreads();
    float rh = (d < HD / 2) ? -sv[d + HD / 2] : sv[d - HD / 2];
    float val = xn * cosT[(size_t)t * HD + d] + rh * sinT[(size_t)t * HD + d];
    __nv_bfloat16 hh, ll;
    split2(val, hh, ll);
    __nv_bfloat16* o = out + ((size_t)h * T2 + t) * (3 * HD);
    o[d] = hh;
    o[HD + d]     = isA ? ll : hh;
    o[2 * HD + d] = isA ? hh : ll;
}

// ================= V -> V^T split bf16 [h][d][3*T2] (B-pattern) =================
__global__ void split_vt(const float* __restrict__ v, __nv_bfloat16* __restrict__ out)
{
    int h = blockIdx.x;
    int d = blockIdx.y;
    __nv_bfloat16* o = out + ((size_t)h * HD + d) * (3 * T2);
    for (int s = threadIdx.x; s < T2; s += 256) {
        float x = v[((size_t)s * NKV + h) * HD + d];
        __nv_bfloat16 hh, ll;
        split2(x, hh, ll);
        o[s] = hh;
        o[T2 + s] = hh;
        o[2 * T2 + s] = ll;
    }
}

// ================= causal softmax -> split bf16 P (A-pattern) =================
// Zero-fill only up to lim2 = ((i>>7)+1)*128 — PV never reads beyond that.
__global__ void softmax_split(float* __restrict__ sc, __nv_bfloat16* __restrict__ pc)
{
    int i = blockIdx.x, h = blockIdx.y;
    float* row = sc + ((size_t)h * T2 + i) * T2;
    __nv_bfloat16* o = pc + ((size_t)h * T2 + i) * (3 * T2);
    int lim = i + 1;
    int lim2 = ((i >> 7) + 1) * 128;
    int tid = threadIdx.x;
    __shared__ float red[8];

    float m = -1e30f;
    for (int j = tid; j < lim; j += 256) m = fmaxf(m, row[j]);
    for (int s = 16; s; s >>= 1) m = fmaxf(m, __shfl_xor_sync(0xffffffffu, m, s));
    if ((tid & 31) == 0) red[tid >> 5] = m;
    __syncthreads();
    if (tid < 8) {
        float v = red[tid];
        for (int s = 4; s; s >>= 1) v = fmaxf(v, __shfl_xor_sync(0xffu, v, s));
        if (tid == 0) red[0] = v;
    }
    __syncthreads();
    float M = red[0];
    __syncthreads();

    float sum = 0.f;
    for (int j = tid; j < lim; j += 256) {
        float e = __expf((row[j] - M) * SCALE);
        row[j] = e;
        sum += e;
    }
    for (int s = 16; s; s >>= 1) sum += __shfl_xor_sync(0xffffffffu, sum, s);
    if ((tid & 31) == 0) red[tid >> 5] = sum;
    __syncthreads();
    if (tid < 8) {
        float v = red[tid];
        for (int s = 4; s; s >>= 1) v += __shfl_xor_sync(0xffu, v, s);
        if (tid == 0) red[0] = v;
    }
    __syncthreads();
    float inv = 1.f / red[0];
    __nv_bfloat16 z = __float2bfloat16_rn(0.f);
    for (int j = tid; j < lim; j += 256) {
        float p = row[j] * inv;
        __nv_bfloat16 hh, ll;
        split2(p, hh, ll);
        o[j] = hh; o[T2 + j] = ll; o[2 * T2 + j] = hh;
    }
    for (int j = lim + tid; j < lim2; j += 256) {
        o[j] = z; o[T2 + j] = z; o[2 * T2 + j] = z;
    }
}

// ================= silu(gate)*up -> split bf16 (A-pattern) =================
__global__ void act_split(const float* __restrict__ gu, __nv_bfloat16* __restrict__ out)
{
    long t = blockIdx.x;
    int i = blockIdx.y * 256 + threadIdx.x;
    float g = gu[t * (2 * II) + i];
    float u = gu[t * (2 * II) + II + i];
    float a = g / (1.f + __expf(-g)) * u;
    __nv_bfloat16 hh, ll;
    split2(a, hh, ll);
    __nv_bfloat16* o = out + t * (3L * II);
    o[i] = hh; o[II + i] = ll; o[2L * II + i] = hh;
}

// ================= launch =================
extern "C" void kernel_launch(void* const* d_in, const int* in_sizes, int n_in,
                              void* d_out, int out_size)
{
    const float* hidden_conv = (const float*)d_in[0];
    const float* cosp = (const float*)d_in[1];
    const float* sinp = (const float*)d_in[2];
    const float* wq  = (const float*)d_in[5];
    const float* wk  = (const float*)d_in[6];
    const float* wv  = (const float*)d_in[7];
    const float* wo  = (const float*)d_in[8];
    const float* wgu = (const float*)d_in[9];
    const float* wd  = (const float*)d_in[10];
    const float* ilw = (const float*)d_in[11];
    const float* plw = (const float*)d_in[12];
    const float* qnw = (const float*)d_in[13];
    const float* knw = (const float*)d_in[14];
    float* out = (float*)d_out;

    float *px, *pq, *pk, *pv, *psc, *pao, *phid, *pgu, *ph2;
    __nv_bfloat16 *ch, *ch2, *cwq, *cwk, *cwv, *cwo, *cwgu, *cwd, *cact, *cq, *ck, *cvt, *cp, *cao;
    cudaGetSymbolAddress((void**)&px,   g_x);
    cudaGetSymbolAddress((void**)&pq,   g_q);
    cudaGetSymbolAddress((void**)&pk,   g_k);
    cudaGetSymbolAddress((void**)&pv,   g_v);
    cudaGetSymbolAddress((void**)&psc,  g_sc);
    cudaGetSymbolAddress((void**)&pao,  g_ao);
    cudaGetSymbolAddress((void**)&phid, g_hid);
    cudaGetSymbolAddress((void**)&pgu,  g_gu);
    cudaGetSymbolAddress((void**)&ph2,  g_h2);
    cudaGetSymbolAddress((void**)&ch,   c_h);
    cudaGetSymbolAddress((void**)&ch2,  c_h2);
    cudaGetSymbolAddress((void**)&cwq,  c_wq);
    cudaGetSymbolAddress((void**)&cwk,  c_wk);
    cudaGetSymbolAddress((void**)&cwv,  c_wv);
    cudaGetSymbolAddress((void**)&cwo,  c_wo);
    cudaGetSymbolAddress((void**)&cwgu, c_wgu);
    cudaGetSymbolAddress((void**)&cwd,  c_wd);
    cudaGetSymbolAddress((void**)&cact, c_act);
    cudaGetSymbolAddress((void**)&cq,   c_q);
    cudaGetSymbolAddress((void**)&ck,   c_k);
    cudaGetSymbolAddress((void**)&cvt,  c_vt);
    cudaGetSymbolAddress((void**)&cp,   c_p);
    cudaGetSymbolAddress((void**)&cao,  c_ao);

    dim3 tb(32, 8);

    split_rm<<<dim3(2048, 4),  256>>>(wq,  cwq,  HIDN, 0);
    split_rm<<<dim3(1024, 4),  256>>>(wk,  cwk,  HIDN, 0);
    split_rm<<<dim3(1024, 4),  256>>>(wv,  cwv,  HIDN, 0);
    transpose_kernel<<<dim3(T2 / 32, HIDN / 32), tb>>>(hidden_conv, px, HIDN, T2);
    rmsnorm_split<<<T2, 256>>>(px, ilw, ch, HIDN);

    // qkv projections (K' = 6144) — grid (m-tiles, n-tiles)
    gemm_bf16<<<dim3(16, 16, 1), 256>>>(ch, cwq, nullptr, pq, 3 * HIDN, 3 * HIDN, 3 * HIDN, NH * HD, 0, 0, 0, 1, 0, 0);
    gemm_bf16<<<dim3(16, 8, 1),  256>>>(ch, cwk, nullptr, pk, 3 * HIDN, 3 * HIDN, 3 * HIDN, NKV * HD, 0, 0, 0, 1, 0, 0);
    gemm_bf16<<<dim3(16, 8, 1),  256>>>(ch, cwv, nullptr, pv, 3 * HIDN, 3 * HIDN, 3 * HIDN, NKV * HD, 0, 0, 0, 1, 0, 0);

    // q/k norm + rope + split-gather; v transpose-split
    qknorm_rope_split<<<dim3(NH, T2),  HD>>>(pq, qnw, cosp, sinp, cq, NH, 1);
    qknorm_rope_split<<<dim3(NKV, T2), HD>>>(pk, knw, cosp, sinp, ck, NKV, 0);
    split_vt<<<dim3(NKV, HD), 256>>>(pv, cvt);

    // scores[h] = Q_h * K_{h/2}^T  (K' = 384) — causal tile skip; grid (m, n, h)
    gemm_bf16<<<dim3(16, 16, NH), 256>>>(cq, ck, nullptr, psc, 3 * HD, 3 * HD, 3 * HD, T2,
                                         (long)T2 * 3 * HD, (long)T2 * 3 * HD, (long)T2 * T2, 2, 1, 0);

    // softmax + P split (zero-fill trimmed to PV-read region)
    softmax_split<<<dim3(T2, NH), 256>>>(psc, cp);

    // attn_out[h] = P_h * V_{h/2}  (K' = 6144, N = 128) — segment-limited K; grid (m, n, h)
    gemm_bf16<<<dim3(16, 1, NH), 256>>>(cp, cvt, nullptr, pao, 3 * T2, 3 * T2, 3 * T2, NH * HD,
                                        (long)T2 * 3 * T2, (long)HD * 3 * T2, (long)HD, 2, 0, T2 / 32);

    // wo split + ao split (A-pattern), then hidden = x + ao @ wo^T
    split_rm<<<dim3(2048, 4), 256>>>(wo, cwo, NH * HD, 0);
    split_rm<<<dim3(2048, 4), 256>>>(pao, cao, NH * HD, 1);
    gemm_bf16<<<dim3(16, 16, 1), 256>>>(cao, cwo, px, phid, 3 * NH * HD, 3 * NH * HD, 3 * NH * HD, HIDN, 0, 0, 0, 1, 0, 0);

    // h2_cat = split(rms(hidden)); gu = h2 @ wgu^T  — grid (16 m, 128 n): B reused via L2
    split_rm<<<dim3(16384, 4), 256>>>(wgu, cwgu, HIDN, 0);
    rmsnorm_split<<<T2, 256>>>(phid, plw, ch2, HIDN);
    gemm_bf16<<<dim3(16, 128, 1), 256>>>(ch2, cwgu, nullptr, pgu, 3 * HIDN, 3 * HIDN, 3 * HIDN, 2 * II, 0, 0, 0, 1, 0, 0);

    // act = split(silu(gate)*up); final = hidden + act @ wd^T
    split_rm<<<dim3(2048, 16), 256>>>(wd, cwd, II, 0);
    act_split<<<dim3(T2, II / 256), 256>>>(pgu, cact);
    gemm_bf16<<<dim3(16, 16, 1), 256>>>(cact, cwd, phid, ph2, 3 * II, 3 * II, 3 * II, HIDN, 0, 0, 0, 1, 0, 0);

    // out = final.T
    transpose_kernel<<<dim3(HIDN / 32, T2 / 32), tb>>>(ph2, out, T2, HIDN);
}